// round 1
// baseline (speedup 1.0000x reference)
#include <cuda_runtime.h>

#define MODEL_DIM 768
#define N_HEAD 12
#define HEAD_DIM 64
#define BATCH 2
#define SEQ 2048
#define M_TOT (BATCH * SEQ)   /* 4096 */
#define BHEADS (BATCH * N_HEAD) /* 24 */

// -------- device scratch (no allocations allowed) --------
__device__ float g_qh[BHEADS * SEQ * HEAD_DIM];
__device__ float g_kh[BHEADS * SEQ * HEAD_DIM];
__device__ float g_vh[BHEADS * SEQ * HEAD_DIM];
__device__ float g_ctx[M_TOT * MODEL_DIM];

// ============================================================
// Generic GEMM: C = A @ W^T + bias
//   A [M,K] row-major, W [N,K] row-major.
//   HEADSPLIT: write C in [B, H, S, Dh] layout instead of [M, N].
// 64x64 tile, 256 threads, 4x4 micro-tile, K-chunks of 16.
// ============================================================
template <bool HEADSPLIT>
__global__ void gemm_bias_kernel(const float* __restrict__ A,
                                 const float* __restrict__ W,
                                 const float* __restrict__ bias,
                                 float* __restrict__ C,
                                 int M, int N, int K)
{
    __shared__ float As[16][66];  // [k][m]
    __shared__ float Ws[16][66];  // [k][n]

    const int tid = threadIdx.x;
    const int tx = tid & 15;
    const int ty = tid >> 4;
    const int m0 = blockIdx.x * 64;
    const int n0 = blockIdx.y * 64;

    float acc[4][4] = {};

    for (int k0 = 0; k0 < K; k0 += 16) {
#pragma unroll
        for (int l = 0; l < 4; l++) {
            int e = tid + l * 256;      // 0..1023
            int mm = e >> 4;            // 0..63
            int kk = e & 15;            // 0..15
            As[kk][mm] = A[(long)(m0 + mm) * K + k0 + kk];
            Ws[kk][mm] = W[(long)(n0 + mm) * K + k0 + kk];
        }
        __syncthreads();
#pragma unroll
        for (int kk = 0; kk < 16; kk++) {
            float a[4], w[4];
#pragma unroll
            for (int i = 0; i < 4; i++) a[i] = As[kk][ty * 4 + i];
#pragma unroll
            for (int j = 0; j < 4; j++) w[j] = Ws[kk][tx * 4 + j];
#pragma unroll
            for (int i = 0; i < 4; i++)
#pragma unroll
                for (int j = 0; j < 4; j++)
                    acc[i][j] += a[i] * w[j];
        }
        __syncthreads();
    }

#pragma unroll
    for (int i = 0; i < 4; i++) {
        int m = m0 + ty * 4 + i;
#pragma unroll
        for (int j = 0; j < 4; j++) {
            int n = n0 + tx * 4 + j;
            float v = acc[i][j] + bias[n];
            if (HEADSPLIT) {
                int b = m / SEQ, s = m % SEQ;
                int h = n / HEAD_DIM, d = n % HEAD_DIM;
                C[(((long)(b * N_HEAD + h) * SEQ) + s) * HEAD_DIM + d] = v;
            } else {
                C[(long)m * N + n] = v;
            }
        }
    }
}

// ============================================================
// Fused attention: per block = one (b,h) and 16 query rows.
// Scores tile 16x2048 held in SMEM (padded LD for bank-conflict-
// free column access), softmax in SMEM, PV accumulated from SMEM.
// P written to gmem ONLY because attn_weights is a kernel output.
// ============================================================
#define SROWS 16
#define SC_LD 2050            /* 2048 + 2 -> row stride % 32 == 2: conflict-free cross-row reads */
#define QS_LD 66
#define KS_LD 132             /* K chunk transposed [kk][col], 528B rows (16B aligned) */
#define VS_LD 68              /* V chunk [row][d], 272B rows (16B aligned) */
#define CCHUNK 128
#define ATTN_SMEM_FLOATS (SROWS * SC_LD + SROWS * QS_LD + CCHUNK * VS_LD)
#define ATTN_SMEM_BYTES (ATTN_SMEM_FLOATS * 4)

__global__ void attn_kernel(const float* __restrict__ Qh,
                            const float* __restrict__ Kh,
                            const float* __restrict__ Vh,
                            float* __restrict__ attn_out,  // nullable
                            float* __restrict__ ctx)
{
    extern __shared__ float smem[];
    float* sc = smem;                      // [SROWS][SC_LD]
    float* qs = sc + SROWS * SC_LD;        // [SROWS][QS_LD]
    float* ks = qs + SROWS * QS_LD;        // K: [64][KS_LD]  /  V: [128][VS_LD]

    const int tid = threadIdx.x;           // 256 threads
    const int bh = blockIdx.y;
    const int r0 = blockIdx.x * SROWS;

    // ---- load Q tile ----
    const long qbase = ((long)bh * SEQ + r0) * HEAD_DIM;
    for (int e = tid; e < SROWS * HEAD_DIM; e += 256) {
        int r = e >> 6, d = e & 63;
        qs[r * QS_LD + d] = Qh[qbase + (long)r * HEAD_DIM + d];
    }

    // ---- phase A: scores = scale * Q @ K^T into sc ----
    const int rA = tid >> 4;   // query row 0..15
    const int cgA = tid & 15;  // column group (8 cols)
    for (int c0 = 0; c0 < SEQ; c0 += CCHUNK) {
        __syncthreads();
        // load K chunk transposed: ks[kk][col]
        for (int l = 0; l < (CCHUNK * HEAD_DIM) / 256; l++) {
            int e = tid + l * 256;
            int col = e >> 6, kk = e & 63;
            ks[kk * KS_LD + col] = Kh[((long)bh * SEQ + c0 + col) * HEAD_DIM + kk];
        }
        __syncthreads();
        float acc[8] = {};
#pragma unroll 8
        for (int kk = 0; kk < HEAD_DIM; kk++) {
            float qv = qs[rA * QS_LD + kk];
            const float4* krow = reinterpret_cast<const float4*>(&ks[kk * KS_LD]);
            float4 kA = krow[cgA * 2];
            float4 kB = krow[cgA * 2 + 1];
            acc[0] += qv * kA.x; acc[1] += qv * kA.y;
            acc[2] += qv * kA.z; acc[3] += qv * kA.w;
            acc[4] += qv * kB.x; acc[5] += qv * kB.y;
            acc[6] += qv * kB.z; acc[7] += qv * kB.w;
        }
#pragma unroll
        for (int j = 0; j < 8; j++)
            sc[rA * SC_LD + c0 + cgA * 8 + j] = acc[j] * 0.125f;  // 1/sqrt(64)
    }
    __syncthreads();

    // ---- phase B: softmax per row (8 warps x 2 rows) ----
    const int warp = tid >> 5, lane = tid & 31;
    for (int rr = 0; rr < 2; rr++) {
        int r = warp + rr * 8;
        float* row = sc + r * SC_LD;
        float mx = -1e30f;
        for (int i = lane; i < SEQ; i += 32) mx = fmaxf(mx, row[i]);
#pragma unroll
        for (int o = 16; o > 0; o >>= 1) mx = fmaxf(mx, __shfl_xor_sync(0xffffffffu, mx, o));
        float sum = 0.f;
        for (int i = lane; i < SEQ; i += 32) {
            float e = __expf(row[i] - mx);
            row[i] = e;
            sum += e;
        }
#pragma unroll
        for (int o = 16; o > 0; o >>= 1) sum += __shfl_xor_sync(0xffffffffu, sum, o);
        float inv = 1.f / sum;
        if (attn_out) {
            float* orow = attn_out + ((long)bh * SEQ + r0 + r) * SEQ;
            for (int i = lane; i < SEQ; i += 32) {
                float p = row[i] * inv;
                row[i] = p;
                orow[i] = p;
            }
        } else {
            for (int i = lane; i < SEQ; i += 32) row[i] *= inv;
        }
    }

    // ---- phase C: ctx = P @ V ----
    const int rC = tid & 15;   // query row
    const int c4 = tid >> 4;   // 4-wide column group in Dh
    float acc[4] = {};
    for (int c0 = 0; c0 < SEQ; c0 += CCHUNK) {
        __syncthreads();
        for (int l = 0; l < (CCHUNK * HEAD_DIM) / 256; l++) {
            int e = tid + l * 256;
            int row = e >> 6, d = e & 63;
            ks[row * VS_LD + d] = Vh[((long)bh * SEQ + c0 + row) * HEAD_DIM + d];
        }
        __syncthreads();
#pragma unroll 4
        for (int kk = 0; kk < CCHUNK; kk++) {
            float p = sc[rC * SC_LD + c0 + kk];
            float4 v = reinterpret_cast<const float4*>(&ks[kk * VS_LD])[c4];
            acc[0] += p * v.x; acc[1] += p * v.y;
            acc[2] += p * v.z; acc[3] += p * v.w;
        }
    }
    // write ctx in plain [M, MODEL_DIM] layout
    {
        int b = bh / N_HEAD, h = bh % N_HEAD;
        long base = ((long)(b * SEQ + r0 + rC)) * MODEL_DIM + h * HEAD_DIM + c4 * 4;
        ctx[base + 0] = acc[0];
        ctx[base + 1] = acc[1];
        ctx[base + 2] = acc[2];
        ctx[base + 3] = acc[3];
    }
}

// ============================================================
// Host launch
// ============================================================
extern "C" void kernel_launch(void* const* d_in, const int* in_sizes, int n_in,
                              void* d_out, int out_size)
{
    const float* q    = (const float*)d_in[0];
    const float* k    = (const float*)d_in[1];
    const float* v    = (const float*)d_in[2];
    const float* wq_w = (const float*)d_in[3];
    const float* wq_b = (const float*)d_in[4];
    const float* wk_w = (const float*)d_in[5];
    const float* wk_b = (const float*)d_in[6];
    const float* wv_w = (const float*)d_in[7];
    const float* wv_b = (const float*)d_in[8];
    const float* wo_w = (const float*)d_in[9];
    const float* wo_b = (const float*)d_in[10];
    float* out = (float*)d_out;

    float *qh, *kh, *vh, *ctx;
    cudaGetSymbolAddress((void**)&qh, g_qh);
    cudaGetSymbolAddress((void**)&kh, g_kh);
    cudaGetSymbolAddress((void**)&vh, g_vh);
    cudaGetSymbolAddress((void**)&ctx, g_ctx);

    // Output = [output (M_TOT*MODEL_DIM floats)] ++ [attn_weights (BH*S*S floats)]
    const long out_elems = (long)M_TOT * MODEL_DIM;
    float* attn_ptr = ((long)out_size > out_elems) ? (out + out_elems) : nullptr;

    cudaFuncSetAttribute(attn_kernel,
                         cudaFuncAttributeMaxDynamicSharedMemorySize,
                         ATTN_SMEM_BYTES);

    dim3 gproj(M_TOT / 64, MODEL_DIM / 64);  // (64, 12)
    gemm_bias_kernel<true><<<gproj, 256>>>(q, wq_w, wq_b, qh, M_TOT, MODEL_DIM, MODEL_DIM);
    gemm_bias_kernel<true><<<gproj, 256>>>(k, wk_w, wk_b, kh, M_TOT, MODEL_DIM, MODEL_DIM);
    gemm_bias_kernel<true><<<gproj, 256>>>(v, wv_w, wv_b, vh, M_TOT, MODEL_DIM, MODEL_DIM);

    dim3 gattn(SEQ / SROWS, BHEADS);  // (128, 24)
    attn_kernel<<<gattn, 256, ATTN_SMEM_BYTES>>>(qh, kh, vh, attn_ptr, ctx);

    gemm_bias_kernel<false><<<gproj, 256>>>(ctx, wo_w, wo_b, out, M_TOT, MODEL_DIM, MODEL_DIM);
}

// round 2
// speedup vs baseline: 5.4181x; 5.4181x over previous
#include <cuda_runtime.h>

#define MODEL_DIM 768
#define N_HEAD 12
#define HEAD_DIM 64
#define BATCH 2
#define SEQ 2048
#define M_TOT 4096
#define BHEADS 24

#define PAD_A 132
#define PAD_W 68

typedef unsigned long long u64;
typedef unsigned int u32;

// -------- device scratch (no allocations allowed) --------
__device__ float g_qh[BHEADS * SEQ * HEAD_DIM];
__device__ float g_kh[BHEADS * SEQ * HEAD_DIM];
__device__ float g_vh[BHEADS * SEQ * HEAD_DIM];
__device__ float g_ctx[M_TOT * MODEL_DIM];

// -------- packed f32x2 helpers (Blackwell FFMA2 path) --------
__device__ __forceinline__ u64 pk2(float lo, float hi) {
    u64 r;
    asm("mov.b64 %0, {%1, %2};" : "=l"(r)
        : "r"(__float_as_uint(lo)), "r"(__float_as_uint(hi)));
    return r;
}
__device__ __forceinline__ u64 fma2(u64 a, u64 b, u64 c) {
    u64 d;
    asm("fma.rn.f32x2 %0, %1, %2, %3;" : "=l"(d) : "l"(a), "l"(b), "l"(c));
    return d;
}
__device__ __forceinline__ float lo32(u64 v) { return __uint_as_float((u32)v); }
__device__ __forceinline__ float hi32(u64 v) { return __uint_as_float((u32)(v >> 32)); }

// ============================================================
// GEMM (W-transposed form): C = A @ W^T  (+bias | *scale)
//   A [M,KDIM], W [N,KDIM] row-major.
//   BM=128, BN=64, BK=16, 128 threads, 8x8 micro-tile, FFMA2.
// MODE 0: head-split epilogue + bias (Q/K/V projections)
// MODE 1: plain epilogue + bias     (output projection)
// MODE 2: batched over blockIdx.z, *0.125 scale (QK^T scores)
// ============================================================
template <int KDIM, int MODE>
__global__ void __launch_bounds__(128)
gemm_wt_kernel(const float* __restrict__ Ag, const float* __restrict__ Wg,
               const float* __restrict__ bias, float* __restrict__ Cg)
{
    __shared__ float As[16 * PAD_A];
    __shared__ float Ws[16 * PAD_W];

    const int tid = threadIdx.x;
    const int tx = tid & 7;     // n
    const int ty = tid >> 3;    // m
    const int m0 = blockIdx.x * 128;
    const int n0 = blockIdx.y * 64;

    const float* A;
    const float* W;
    if (MODE == 2) {
        const long boff = (long)blockIdx.z * SEQ * HEAD_DIM;
        A = Ag + boff;
        W = Wg + boff;
    } else {
        A = Ag;
        W = Wg;
    }

    u64 acc[8][4];
#pragma unroll
    for (int i = 0; i < 8; i++)
#pragma unroll
        for (int j = 0; j < 4; j++) acc[i][j] = 0ull;

    for (int k0 = 0; k0 < KDIM; k0 += 16) {
        // A tile 128x16 -> As[k][m]
#pragma unroll
        for (int l = 0; l < 4; l++) {
            int fid = tid + l * 128;        // 0..511 quads
            int m = fid >> 2, kq = fid & 3;
            float4 v = *(const float4*)(A + (long)(m0 + m) * KDIM + k0 + kq * 4);
            As[(kq * 4 + 0) * PAD_A + m] = v.x;
            As[(kq * 4 + 1) * PAD_A + m] = v.y;
            As[(kq * 4 + 2) * PAD_A + m] = v.z;
            As[(kq * 4 + 3) * PAD_A + m] = v.w;
        }
        // W tile 64x16 -> Ws[k][n]
#pragma unroll
        for (int l = 0; l < 2; l++) {
            int fid = tid + l * 128;        // 0..255 quads
            int n = fid >> 2, kq = fid & 3;
            float4 v = *(const float4*)(W + (long)(n0 + n) * KDIM + k0 + kq * 4);
            Ws[(kq * 4 + 0) * PAD_W + n] = v.x;
            Ws[(kq * 4 + 1) * PAD_W + n] = v.y;
            Ws[(kq * 4 + 2) * PAD_W + n] = v.z;
            Ws[(kq * 4 + 3) * PAD_W + n] = v.w;
        }
        __syncthreads();
#pragma unroll
        for (int kk = 0; kk < 16; kk++) {
            const float4 a0 = *(const float4*)&As[kk * PAD_A + ty * 8];
            const float4 a1 = *(const float4*)&As[kk * PAD_A + ty * 8 + 4];
            const float4 w0 = *(const float4*)&Ws[kk * PAD_W + tx * 8];
            const float4 w1 = *(const float4*)&Ws[kk * PAD_W + tx * 8 + 4];
            u64 wp[4] = { pk2(w0.x, w0.y), pk2(w0.z, w0.w),
                          pk2(w1.x, w1.y), pk2(w1.z, w1.w) };
            float av[8] = {a0.x, a0.y, a0.z, a0.w, a1.x, a1.y, a1.z, a1.w};
#pragma unroll
            for (int i = 0; i < 8; i++) {
                u64 ap = pk2(av[i], av[i]);
#pragma unroll
                for (int j = 0; j < 4; j++)
                    acc[i][j] = fma2(ap, wp[j], acc[i][j]);
            }
        }
        __syncthreads();
    }

    // ---- epilogue ----
    float bv[8];
    if (MODE != 2) {
        float4 b0 = *(const float4*)(bias + n0 + tx * 8);
        float4 b1 = *(const float4*)(bias + n0 + tx * 8 + 4);
        bv[0] = b0.x; bv[1] = b0.y; bv[2] = b0.z; bv[3] = b0.w;
        bv[4] = b1.x; bv[5] = b1.y; bv[6] = b1.z; bv[7] = b1.w;
    }
#pragma unroll
    for (int i = 0; i < 8; i++) {
        float r[8];
#pragma unroll
        for (int jp = 0; jp < 4; jp++) {
            r[2 * jp]     = lo32(acc[i][jp]);
            r[2 * jp + 1] = hi32(acc[i][jp]);
        }
        if (MODE == 2) {
#pragma unroll
            for (int j = 0; j < 8; j++) r[j] *= 0.125f;
        } else {
#pragma unroll
            for (int j = 0; j < 8; j++) r[j] += bv[j];
        }
        const int m = m0 + ty * 8 + i;
        float* dst;
        if (MODE == 0) {
            const int b = m >> 11;          // / SEQ
            const int s = m & (SEQ - 1);
            const int h = n0 >> 6;          // tile is one head wide
            dst = Cg + (((long)(b * N_HEAD + h) * SEQ) + s) * HEAD_DIM + tx * 8;
        } else if (MODE == 1) {
            dst = Cg + (long)m * MODEL_DIM + n0 + tx * 8;
        } else {
            dst = Cg + (long)blockIdx.z * SEQ * SEQ + (long)m * SEQ + n0 + tx * 8;
        }
        *(float4*)dst       = make_float4(r[0], r[1], r[2], r[3]);
        *(float4*)(dst + 4) = make_float4(r[4], r[5], r[6], r[7]);
    }
}

// ============================================================
// PV GEMM: ctx = P @ V per head.  P [SEQ,SEQ], V [SEQ,64].
// Same tiling; V tile loads direct (already [k][n]).
// ============================================================
__global__ void __launch_bounds__(128)
pv_kernel(const float* __restrict__ Pg, const float* __restrict__ Vg,
          float* __restrict__ ctx)
{
    __shared__ float As[16 * PAD_A];
    __shared__ float Ws[16 * PAD_W];

    const int tid = threadIdx.x;
    const int tx = tid & 7;
    const int ty = tid >> 3;
    const int m0 = blockIdx.x * 128;
    const int bh = blockIdx.y;

    const float* P = Pg + (long)bh * SEQ * SEQ;
    const float* V = Vg + (long)bh * SEQ * HEAD_DIM;

    u64 acc[8][4];
#pragma unroll
    for (int i = 0; i < 8; i++)
#pragma unroll
        for (int j = 0; j < 4; j++) acc[i][j] = 0ull;

    for (int k0 = 0; k0 < SEQ; k0 += 16) {
        // P tile 128x16 -> As[k][m]
#pragma unroll
        for (int l = 0; l < 4; l++) {
            int fid = tid + l * 128;
            int m = fid >> 2, kq = fid & 3;
            float4 v = *(const float4*)(P + (long)(m0 + m) * SEQ + k0 + kq * 4);
            As[(kq * 4 + 0) * PAD_A + m] = v.x;
            As[(kq * 4 + 1) * PAD_A + m] = v.y;
            As[(kq * 4 + 2) * PAD_A + m] = v.z;
            As[(kq * 4 + 3) * PAD_A + m] = v.w;
        }
        // V tile 16x64 -> Ws[k][n] (direct)
#pragma unroll
        for (int l = 0; l < 2; l++) {
            int fid = tid + l * 128;        // 256 quads: 16 rows x 16 quads
            int kr = fid >> 4, nq = fid & 15;
            float4 v = *(const float4*)(V + (long)(k0 + kr) * HEAD_DIM + nq * 4);
            *(float4*)&Ws[kr * PAD_W + nq * 4] = v;
        }
        __syncthreads();
#pragma unroll
        for (int kk = 0; kk < 16; kk++) {
            const float4 a0 = *(const float4*)&As[kk * PAD_A + ty * 8];
            const float4 a1 = *(const float4*)&As[kk * PAD_A + ty * 8 + 4];
            const float4 w0 = *(const float4*)&Ws[kk * PAD_W + tx * 8];
            const float4 w1 = *(const float4*)&Ws[kk * PAD_W + tx * 8 + 4];
            u64 wp[4] = { pk2(w0.x, w0.y), pk2(w0.z, w0.w),
                          pk2(w1.x, w1.y), pk2(w1.z, w1.w) };
            float av[8] = {a0.x, a0.y, a0.z, a0.w, a1.x, a1.y, a1.z, a1.w};
#pragma unroll
            for (int i = 0; i < 8; i++) {
                u64 ap = pk2(av[i], av[i]);
#pragma unroll
                for (int j = 0; j < 4; j++)
                    acc[i][j] = fma2(ap, wp[j], acc[i][j]);
            }
        }
        __syncthreads();
    }

    const int b = bh / N_HEAD;
    const int h = bh % N_HEAD;
#pragma unroll
    for (int i = 0; i < 8; i++) {
        float r[8];
#pragma unroll
        for (int jp = 0; jp < 4; jp++) {
            r[2 * jp]     = lo32(acc[i][jp]);
            r[2 * jp + 1] = hi32(acc[i][jp]);
        }
        const int m = m0 + ty * 8 + i;
        float* dst = ctx + ((long)(b * SEQ + m)) * MODEL_DIM + h * HEAD_DIM + tx * 8;
        *(float4*)dst       = make_float4(r[0], r[1], r[2], r[3]);
        *(float4*)(dst + 4) = make_float4(r[4], r[5], r[6], r[7]);
    }
}

// ============================================================
// Softmax: in-place over rows of 2048. FMA-pipe exp (no MUFU).
// ============================================================
__device__ __forceinline__ float fast_exp(float x)
{
    const float L2E = 1.4426950408889634f;
    float t = fmaf(x, L2E, 12582912.0f);          // round(x*log2e) via magic
    int e = __float_as_int(t) - 0x4B400000;
    float fi = t - 12582912.0f;
    float f = fmaf(x, L2E, -fi);                  // frac in [-0.5, 0.5]
    float p = 1.53953850e-4f;                     // ln2^6/720
    p = fmaf(p, f, 1.33335581e-3f);
    p = fmaf(p, f, 9.61812911e-3f);
    p = fmaf(p, f, 5.55041087e-2f);
    p = fmaf(p, f, 2.40226507e-1f);
    p = fmaf(p, f, 6.93147181e-1f);
    p = fmaf(p, f, 1.0f);
    return __int_as_float(__float_as_int(p) + (e << 23));
}

__global__ void __launch_bounds__(256)
softmax_kernel(float* __restrict__ S)
{
    __shared__ float red[8];
    const long row = blockIdx.x;
    float4* p = (float4*)(S + row * SEQ);
    const int tid = threadIdx.x;
    const int lane = tid & 31, warp = tid >> 5;

    float4 a = p[tid];
    float4 b = p[tid + 256];

    float mx = fmaxf(fmaxf(fmaxf(a.x, a.y), fmaxf(a.z, a.w)),
                     fmaxf(fmaxf(b.x, b.y), fmaxf(b.z, b.w)));
#pragma unroll
    for (int o = 16; o; o >>= 1) mx = fmaxf(mx, __shfl_xor_sync(0xffffffffu, mx, o));
    if (lane == 0) red[warp] = mx;
    __syncthreads();
    float rm = red[0];
#pragma unroll
    for (int i = 1; i < 8; i++) rm = fmaxf(rm, red[i]);

    a.x = fast_exp(a.x - rm); a.y = fast_exp(a.y - rm);
    a.z = fast_exp(a.z - rm); a.w = fast_exp(a.w - rm);
    b.x = fast_exp(b.x - rm); b.y = fast_exp(b.y - rm);
    b.z = fast_exp(b.z - rm); b.w = fast_exp(b.w - rm);

    float s = (a.x + a.y) + (a.z + a.w) + (b.x + b.y) + (b.z + b.w);
#pragma unroll
    for (int o = 16; o; o >>= 1) s += __shfl_xor_sync(0xffffffffu, s, o);
    __syncthreads();                 // protect red[] reuse
    if (lane == 0) red[warp] = s;
    __syncthreads();
    float tot = red[0];
#pragma unroll
    for (int i = 1; i < 8; i++) tot += red[i];
    float inv = 1.0f / tot;

    a.x *= inv; a.y *= inv; a.z *= inv; a.w *= inv;
    b.x *= inv; b.y *= inv; b.z *= inv; b.w *= inv;
    p[tid] = a;
    p[tid + 256] = b;
}

// ============================================================
// Host launch
// ============================================================
extern "C" void kernel_launch(void* const* d_in, const int* in_sizes, int n_in,
                              void* d_out, int out_size)
{
    const float* q    = (const float*)d_in[0];
    const float* k    = (const float*)d_in[1];
    const float* v    = (const float*)d_in[2];
    const float* wq_w = (const float*)d_in[3];
    const float* wq_b = (const float*)d_in[4];
    const float* wk_w = (const float*)d_in[5];
    const float* wk_b = (const float*)d_in[6];
    const float* wv_w = (const float*)d_in[7];
    const float* wv_b = (const float*)d_in[8];
    const float* wo_w = (const float*)d_in[9];
    const float* wo_b = (const float*)d_in[10];
    float* out = (float*)d_out;

    float *qh, *kh, *vh, *ctx;
    cudaGetSymbolAddress((void**)&qh, g_qh);
    cudaGetSymbolAddress((void**)&kh, g_kh);
    cudaGetSymbolAddress((void**)&vh, g_vh);
    cudaGetSymbolAddress((void**)&ctx, g_ctx);

    // d_out = [output (4096*768)] ++ [attn_weights (24*2048*2048)]
    float* attnW = out + (long)M_TOT * MODEL_DIM;

    dim3 gproj(M_TOT / 128, MODEL_DIM / 64);          // (32, 12)
    gemm_wt_kernel<MODEL_DIM, 0><<<gproj, 128>>>(q, wq_w, wq_b, qh);
    gemm_wt_kernel<MODEL_DIM, 0><<<gproj, 128>>>(k, wk_w, wk_b, kh);
    gemm_wt_kernel<MODEL_DIM, 0><<<gproj, 128>>>(v, wv_w, wv_b, vh);

    dim3 gsc(SEQ / 128, SEQ / 64, BHEADS);            // (16, 32, 24)
    gemm_wt_kernel<HEAD_DIM, 2><<<gsc, 128>>>(qh, kh, nullptr, attnW);

    softmax_kernel<<<BHEADS * SEQ, 256>>>(attnW);     // 49152 rows, in-place

    dim3 gpv(SEQ / 128, BHEADS);                      // (16, 24)
    pv_kernel<<<gpv, 128>>>(attnW, vh, ctx);

    gemm_wt_kernel<MODEL_DIM, 1><<<gproj, 128>>>(ctx, wo_w, wo_b, out);
}

// round 4
// speedup vs baseline: 8.5395x; 1.5761x over previous
#include <cuda_runtime.h>
#include <cuda_bf16.h>

#define MODEL_DIM 768
#define N_HEAD 12
#define HEAD_DIM 64
#define SEQ 2048
#define M_TOT 4096
#define BHEADS 24

typedef unsigned int u32;

// -------- device scratch (no allocations allowed) --------
__device__ float g_qh[BHEADS * SEQ * HEAD_DIM];
__device__ float g_kh[BHEADS * SEQ * HEAD_DIM];
__device__ float g_vh[BHEADS * SEQ * HEAD_DIM];
__device__ float g_ctx[M_TOT * MODEL_DIM];

// ============================================================
// helpers
// ============================================================
__device__ __forceinline__ u32 smem_u32(const void* p) {
    u32 a;
    asm("{ .reg .u64 t; cvta.to.shared.u64 t, %1; cvt.u32.u64 %0, t; }"
        : "=r"(a) : "l"(p));
    return a;
}

__device__ __forceinline__ void ldsm4(u32& r0, u32& r1, u32& r2, u32& r3, u32 addr) {
    asm volatile("ldmatrix.sync.aligned.m8n8.x4.shared.b16 {%0,%1,%2,%3}, [%4];"
        : "=r"(r0), "=r"(r1), "=r"(r2), "=r"(r3) : "r"(addr));
}

__device__ __forceinline__ void mma_bf16(float* c, u32 a0, u32 a1, u32 a2, u32 a3,
                                         u32 b0, u32 b1) {
    asm volatile(
        "mma.sync.aligned.m16n8k16.row.col.f32.bf16.bf16.f32 "
        "{%0,%1,%2,%3}, {%4,%5,%6,%7}, {%8,%9}, {%0,%1,%2,%3};"
        : "+f"(c[0]), "+f"(c[1]), "+f"(c[2]), "+f"(c[3])
        : "r"(a0), "r"(a1), "r"(a2), "r"(a3), "r"(b0), "r"(b1));
}

__device__ __forceinline__ u32 pack_bf2(__nv_bfloat16 a, __nv_bfloat16 b) {
    __nv_bfloat162 p(a, b);
    return *reinterpret_cast<u32*>(&p);
}

__device__ __forceinline__ void cvt_split(float x, __nv_bfloat16& h, __nv_bfloat16& l) {
    h = __float2bfloat16_rn(x);
    l = __float2bfloat16_rn(x - __bfloat162float(h));
}

// ============================================================
// split-bf16 mma.sync GEMM:  C = A @ B^T
//   A [M,K] row-major, B [N,K] row-major (= col-major KxN for mma)
// MODE 0: head-split + bias  (Q/K/V projections)
// MODE 1: plain + bias       (output projection)
// MODE 2: *0.125, batched per head (scores)
// MODE 3: PV (B = V [K,64], transposed on load), batched per head
// Block: 128 x BN, BK=32, 256 threads.
// ============================================================
#define LDT 40   /* smem tile stride in bf16 (80B rows: ldmatrix conflict-free) */

template <int MODE>
__global__ void __launch_bounds__(256)
mma_gemm(const float* __restrict__ Ag, const float* __restrict__ Bg,
         const float* __restrict__ bias, float* __restrict__ Cg, int KDIM)
{
    constexpr int BN = (MODE == 3) ? 64 : 128;
    constexpr int MT = (MODE == 3) ? 2 : 4;      // 16-row m-tiles per warp
    constexpr int WM = (MODE == 3) ? 32 : 64;

    __shared__ __align__(16) __nv_bfloat16 sAh[128 * LDT];
    __shared__ __align__(16) __nv_bfloat16 sAl[128 * LDT];
    __shared__ __align__(16) __nv_bfloat16 sBh[BN * LDT];
    __shared__ __align__(16) __nv_bfloat16 sBl[BN * LDT];

    const int tid = threadIdx.x;
    const int wid = tid >> 5;
    const int lane = tid & 31;
    const int m0 = blockIdx.x * 128;
    const int n0 = blockIdx.y * BN;
    const int z = blockIdx.z;

    const int warp_m = (MODE == 3) ? (wid >> 1) : (wid >> 2);
    const int warp_n = (MODE == 3) ? (wid & 1) : (wid & 3);
    const int wm0 = warp_m * WM;
    const int wn0 = warp_n * 32;

    const float* A;
    const float* B;
    if (MODE == 2) {
        A = Ag + (long)z * SEQ * HEAD_DIM;
        B = Bg + (long)z * SEQ * HEAD_DIM;
    } else if (MODE == 3) {
        A = Ag + (long)z * SEQ * SEQ;
        B = Bg + (long)z * SEQ * HEAD_DIM;
    } else {
        A = Ag;
        B = Bg;
    }

    const u32 aH = smem_u32(sAh), aL = smem_u32(sAl);
    const u32 bH = smem_u32(sBh), bL = smem_u32(sBl);

    float acc[MT][4][4];
#pragma unroll
    for (int i = 0; i < MT; i++)
#pragma unroll
        for (int j = 0; j < 4; j++)
#pragma unroll
            for (int e = 0; e < 4; e++) acc[i][j][e] = 0.f;

    const int nchunks = KDIM >> 5;
    for (int c = 0; c < nchunks; c++) {
        // ---- A tile 128x32: load fp32, split to hi/lo bf16 ----
#pragma unroll
        for (int g = 0; g < 4; g++) {
            int id = tid + g * 256;
            int row = id >> 3, q = id & 7;
            float4 v = *(const float4*)(A + (long)(m0 + row) * KDIM + c * 32 + q * 4);
            __nv_bfloat16 h0, h1, h2, h3, l0, l1, l2, l3;
            cvt_split(v.x, h0, l0); cvt_split(v.y, h1, l1);
            cvt_split(v.z, h2, l2); cvt_split(v.w, h3, l3);
            uint2 hv = make_uint2(pack_bf2(h0, h1), pack_bf2(h2, h3));
            uint2 lv = make_uint2(pack_bf2(l0, l1), pack_bf2(l2, l3));
            *(uint2*)&sAh[row * LDT + q * 4] = hv;
            *(uint2*)&sAl[row * LDT + q * 4] = lv;
        }
        // ---- B tile ----
        if (MODE == 3) {
            // V chunk [32 k][64 n] -> sB[n][k] transposed
#pragma unroll
            for (int g = 0; g < 2; g++) {
                int id = tid + g * 256;          // 512 quads
                int k = id >> 4, nq = id & 15;
                float4 v = *(const float4*)(B + (long)(c * 32 + k) * HEAD_DIM + nq * 4);
                float xs[4] = {v.x, v.y, v.z, v.w};
#pragma unroll
                for (int e = 0; e < 4; e++) {
                    __nv_bfloat16 h, l;
                    cvt_split(xs[e], h, l);
                    int n = nq * 4 + e;
                    sBh[n * LDT + k] = h;
                    sBl[n * LDT + k] = l;
                }
            }
        } else {
#pragma unroll
            for (int g = 0; g < 4; g++) {
                int id = tid + g * 256;
                int row = id >> 3, q = id & 7;
                float4 v = *(const float4*)(B + (long)(n0 + row) * KDIM + c * 32 + q * 4);
                __nv_bfloat16 h0, h1, h2, h3, l0, l1, l2, l3;
                cvt_split(v.x, h0, l0); cvt_split(v.y, h1, l1);
                cvt_split(v.z, h2, l2); cvt_split(v.w, h3, l3);
                uint2 hv = make_uint2(pack_bf2(h0, h1), pack_bf2(h2, h3));
                uint2 lv = make_uint2(pack_bf2(l0, l1), pack_bf2(l2, l3));
                *(uint2*)&sBh[row * LDT + q * 4] = hv;
                *(uint2*)&sBl[row * LDT + q * 4] = lv;
            }
        }
        __syncthreads();

        // ---- compute: 2 k-steps of 16 ----
#pragma unroll
        for (int ks = 0; ks < 2; ks++) {
            const int k0 = ks * 16;
            u32 ah[MT][4], al[MT][4], bh[4][2], bl[4][2];
#pragma unroll
            for (int mt = 0; mt < MT; mt++) {
                u32 off = (u32)(((wm0 + mt * 16 + (lane & 15)) * LDT
                                 + k0 + (lane >> 4) * 8) * 2);
                ldsm4(ah[mt][0], ah[mt][1], ah[mt][2], ah[mt][3], aH + off);
                ldsm4(al[mt][0], al[mt][1], al[mt][2], al[mt][3], aL + off);
            }
#pragma unroll
            for (int np = 0; np < 2; np++) {
                u32 off = (u32)(((wn0 + np * 16 + (lane & 7) + ((lane >> 4) << 3)) * LDT
                                 + k0 + ((lane >> 3) & 1) * 8) * 2);
                u32 r0, r1, r2, r3;
                ldsm4(r0, r1, r2, r3, bH + off);
                bh[2 * np][0] = r0; bh[2 * np][1] = r1;
                bh[2 * np + 1][0] = r2; bh[2 * np + 1][1] = r3;
                ldsm4(r0, r1, r2, r3, bL + off);
                bl[2 * np][0] = r0; bl[2 * np][1] = r1;
                bl[2 * np + 1][0] = r2; bl[2 * np + 1][1] = r3;
            }
            // product-major passes: consecutive mmas hit distinct accumulators
#pragma unroll
            for (int mt = 0; mt < MT; mt++)
#pragma unroll
                for (int nt = 0; nt < 4; nt++)
                    mma_bf16(acc[mt][nt], ah[mt][0], ah[mt][1], ah[mt][2], ah[mt][3],
                             bh[nt][0], bh[nt][1]);
#pragma unroll
            for (int mt = 0; mt < MT; mt++)
#pragma unroll
                for (int nt = 0; nt < 4; nt++)
                    mma_bf16(acc[mt][nt], ah[mt][0], ah[mt][1], ah[mt][2], ah[mt][3],
                             bl[nt][0], bl[nt][1]);
#pragma unroll
            for (int mt = 0; mt < MT; mt++)
#pragma unroll
                for (int nt = 0; nt < 4; nt++)
                    mma_bf16(acc[mt][nt], al[mt][0], al[mt][1], al[mt][2], al[mt][3],
                             bh[nt][0], bh[nt][1]);
        }
        __syncthreads();
    }

    // ---- epilogue ----
    const int r_lo = lane >> 2;
    const int cp = (lane & 3) * 2;
#pragma unroll
    for (int mt = 0; mt < MT; mt++) {
#pragma unroll
        for (int nt = 0; nt < 4; nt++) {
            const int n = n0 + wn0 + nt * 8 + cp;
#pragma unroll
            for (int half = 0; half < 2; half++) {
                const int m = m0 + wm0 + mt * 16 + r_lo + half * 8;
                float c0 = acc[mt][nt][half * 2];
                float c1 = acc[mt][nt][half * 2 + 1];
                float* dst;
                if (MODE == 0) {
                    c0 += bias[n]; c1 += bias[n + 1];
                    int b = m >> 11, s = m & (SEQ - 1);
                    int h = n >> 6, d = n & 63;
                    dst = Cg + (((long)(b * N_HEAD + h) * SEQ) + s) * HEAD_DIM + d;
                } else if (MODE == 1) {
                    c0 += bias[n]; c1 += bias[n + 1];
                    dst = Cg + (long)m * MODEL_DIM + n;
                } else if (MODE == 2) {
                    c0 *= 0.125f; c1 *= 0.125f;
                    dst = Cg + (long)z * SEQ * SEQ + (long)m * SEQ + n;
                } else {
                    int b = z / N_HEAD, h = z % N_HEAD;
                    dst = Cg + ((long)(b * SEQ + m)) * MODEL_DIM + h * HEAD_DIM + n;
                }
                *(float2*)dst = make_float2(c0, c1);
            }
        }
    }
}

// ============================================================
// Softmax: in-place over rows of 2048. FMA-pipe exp (no MUFU).
// ============================================================
__device__ __forceinline__ float fast_exp(float x)
{
    const float L2E = 1.4426950408889634f;
    float t = fmaf(x, L2E, 12582912.0f);
    int e = __float_as_int(t) - 0x4B400000;
    float fi = t - 12582912.0f;
    float f = fmaf(x, L2E, -fi);
    float p = 1.53953850e-4f;
    p = fmaf(p, f, 1.33335581e-3f);
    p = fmaf(p, f, 9.61812911e-3f);
    p = fmaf(p, f, 5.55041087e-2f);
    p = fmaf(p, f, 2.40226507e-1f);
    p = fmaf(p, f, 6.93147181e-1f);
    p = fmaf(p, f, 1.0f);
    return __int_as_float(__float_as_int(p) + (e << 23));
}

__global__ void __launch_bounds__(256)
softmax_kernel(float* __restrict__ S)
{
    __shared__ float red[8];
    const long row = blockIdx.x;
    float4* p = (float4*)(S + row * SEQ);
    const int tid = threadIdx.x;
    const int lane = tid & 31, warp = tid >> 5;

    float4 a = p[tid];
    float4 b = p[tid + 256];

    float mx = fmaxf(fmaxf(fmaxf(a.x, a.y), fmaxf(a.z, a.w)),
                     fmaxf(fmaxf(b.x, b.y), fmaxf(b.z, b.w)));
#pragma unroll
    for (int o = 16; o; o >>= 1) mx = fmaxf(mx, __shfl_xor_sync(0xffffffffu, mx, o));
    if (lane == 0) red[warp] = mx;
    __syncthreads();
    float rm = red[0];
#pragma unroll
    for (int i = 1; i < 8; i++) rm = fmaxf(rm, red[i]);

    a.x = fast_exp(a.x - rm); a.y = fast_exp(a.y - rm);
    a.z = fast_exp(a.z - rm); a.w = fast_exp(a.w - rm);
    b.x = fast_exp(b.x - rm); b.y = fast_exp(b.y - rm);
    b.z = fast_exp(b.z - rm); b.w = fast_exp(b.w - rm);

    float s = (a.x + a.y) + (a.z + a.w) + (b.x + b.y) + (b.z + b.w);
#pragma unroll
    for (int o = 16; o; o >>= 1) s += __shfl_xor_sync(0xffffffffu, s, o);
    __syncthreads();
    if (lane == 0) red[warp] = s;
    __syncthreads();
    float tot = red[0];
#pragma unroll
    for (int i = 1; i < 8; i++) tot += red[i];
    float inv = 1.0f / tot;

    a.x *= inv; a.y *= inv; a.z *= inv; a.w *= inv;
    b.x *= inv; b.y *= inv; b.z *= inv; b.w *= inv;
    p[tid] = a;
    p[tid + 256] = b;
}

// ============================================================
// Host launch
// ============================================================
extern "C" void kernel_launch(void* const* d_in, const int* in_sizes, int n_in,
                              void* d_out, int out_size)
{
    const float* q    = (const float*)d_in[0];
    const float* k    = (const float*)d_in[1];
    const float* v    = (const float*)d_in[2];
    const float* wq_w = (const float*)d_in[3];
    const float* wq_b = (const float*)d_in[4];
    const float* wk_w = (const float*)d_in[5];
    const float* wk_b = (const float*)d_in[6];
    const float* wv_w = (const float*)d_in[7];
    const float* wv_b = (const float*)d_in[8];
    const float* wo_w = (const float*)d_in[9];
    const float* wo_b = (const float*)d_in[10];
    float* out = (float*)d_out;

    float *qh, *kh, *vh, *ctx;
    cudaGetSymbolAddress((void**)&qh, g_qh);
    cudaGetSymbolAddress((void**)&kh, g_kh);
    cudaGetSymbolAddress((void**)&vh, g_vh);
    cudaGetSymbolAddress((void**)&ctx, g_ctx);

    float* attnW = out + (long)M_TOT * MODEL_DIM;

    dim3 gproj(M_TOT / 128, MODEL_DIM / 128, 1);          // (32, 6)
    mma_gemm<0><<<gproj, 256>>>(q, wq_w, wq_b, qh, MODEL_DIM);
    mma_gemm<0><<<gproj, 256>>>(k, wk_w, wk_b, kh, MODEL_DIM);
    mma_gemm<0><<<gproj, 256>>>(v, wv_w, wv_b, vh, MODEL_DIM);

    dim3 gsc(SEQ / 128, SEQ / 128, BHEADS);               // (16, 16, 24)
    mma_gemm<2><<<gsc, 256>>>(qh, kh, nullptr, attnW, HEAD_DIM);

    softmax_kernel<<<BHEADS * SEQ, 256>>>(attnW);

    dim3 gpv(SEQ / 128, 1, BHEADS);                       // (16, 1, 24)
    mma_gemm<3><<<gpv, 256>>>(attnW, vh, nullptr, ctx, SEQ);

    mma_gemm<1><<<gproj, 256>>>(ctx, wo_w, wo_b, out, MODEL_DIM);
}

// round 5
// speedup vs baseline: 8.6754x; 1.0159x over previous
#include <cuda_runtime.h>
#include <cuda_bf16.h>

#define MODEL_DIM 768
#define N_HEAD 12
#define HEAD_DIM 64
#define SEQ 2048
#define M_TOT 4096
#define BHEADS 24

typedef unsigned int u32;

// -------- device scratch (no allocations allowed) --------
__device__ float g_qh[BHEADS * SEQ * HEAD_DIM];
__device__ float g_kh[BHEADS * SEQ * HEAD_DIM];
__device__ float g_vh[BHEADS * SEQ * HEAD_DIM];
__device__ float g_ctx[M_TOT * MODEL_DIM];

// ============================================================
// helpers
// ============================================================
__device__ __forceinline__ u32 smem_u32(const void* p) {
    u32 a;
    asm("{ .reg .u64 t; cvta.to.shared.u64 t, %1; cvt.u32.u64 %0, t; }"
        : "=r"(a) : "l"(p));
    return a;
}

__device__ __forceinline__ void ldsm4(u32& r0, u32& r1, u32& r2, u32& r3, u32 addr) {
    asm volatile("ldmatrix.sync.aligned.m8n8.x4.shared.b16 {%0,%1,%2,%3}, [%4];"
        : "=r"(r0), "=r"(r1), "=r"(r2), "=r"(r3) : "r"(addr));
}

__device__ __forceinline__ void mma_bf16(float* c, u32 a0, u32 a1, u32 a2, u32 a3,
                                         u32 b0, u32 b1) {
    asm volatile(
        "mma.sync.aligned.m16n8k16.row.col.f32.bf16.bf16.f32 "
        "{%0,%1,%2,%3}, {%4,%5,%6,%7}, {%8,%9}, {%0,%1,%2,%3};"
        : "+f"(c[0]), "+f"(c[1]), "+f"(c[2]), "+f"(c[3])
        : "r"(a0), "r"(a1), "r"(a2), "r"(a3), "r"(b0), "r"(b1));
}

#define CP_ASYNC16(d, s) asm volatile("cp.async.cg.shared.global [%0], [%1], 16;" :: "r"(d), "l"(s) : "memory")
#define CP_COMMIT()      asm volatile("cp.async.commit_group;" ::: "memory")
#define CP_WAIT1()       asm volatile("cp.async.wait_group 1;" ::: "memory")
#define CP_WAIT0()       asm volatile("cp.async.wait_group 0;" ::: "memory")

__device__ __forceinline__ u32 pack_bf2(__nv_bfloat16 a, __nv_bfloat16 b) {
    __nv_bfloat162 p(a, b);
    return *reinterpret_cast<u32*>(&p);
}

__device__ __forceinline__ void cvt_split(float x, __nv_bfloat16& h, __nv_bfloat16& l) {
    h = __float2bfloat16_rn(x);
    l = __float2bfloat16_rn(x - __bfloat162float(h));
}

__device__ __forceinline__ float fast_exp(float x)
{
    const float L2E = 1.4426950408889634f;
    float t = fmaf(x, L2E, 12582912.0f);
    int e = __float_as_int(t) - 0x4B400000;
    float fi = t - 12582912.0f;
    float f = fmaf(x, L2E, -fi);
    float p = 1.53953850e-4f;
    p = fmaf(p, f, 1.33335581e-3f);
    p = fmaf(p, f, 9.61812911e-3f);
    p = fmaf(p, f, 5.55041087e-2f);
    p = fmaf(p, f, 2.40226507e-1f);
    p = fmaf(p, f, 6.93147181e-1f);
    p = fmaf(p, f, 1.0f);
    return __int_as_float(__float_as_int(p) + (e << 23));
}

// ============================================================
// split-bf16 mma.sync GEMM (round-4 verified), MODE 1 & 3 only
// MODE 1: plain + bias       (output projection)
// MODE 3: PV (B = V [K,64], transposed on load), batched per head
// ============================================================
#define LDT 40

template <int MODE>
__global__ void __launch_bounds__(256)
mma_gemm(const float* __restrict__ Ag, const float* __restrict__ Bg,
         const float* __restrict__ bias, float* __restrict__ Cg, int KDIM)
{
    constexpr int BN = (MODE == 3) ? 64 : 128;
    constexpr int MT = (MODE == 3) ? 2 : 4;
    constexpr int WM = (MODE == 3) ? 32 : 64;

    __shared__ __align__(16) __nv_bfloat16 sAh[128 * LDT];
    __shared__ __align__(16) __nv_bfloat16 sAl[128 * LDT];
    __shared__ __align__(16) __nv_bfloat16 sBh[BN * LDT];
    __shared__ __align__(16) __nv_bfloat16 sBl[BN * LDT];

    const int tid = threadIdx.x;
    const int wid = tid >> 5;
    const int lane = tid & 31;
    const int m0 = blockIdx.x * 128;
    const int n0 = blockIdx.y * BN;
    const int z = blockIdx.z;

    const int warp_m = (MODE == 3) ? (wid >> 1) : (wid >> 2);
    const int warp_n = (MODE == 3) ? (wid & 1) : (wid & 3);
    const int wm0 = warp_m * WM;
    const int wn0 = warp_n * 32;

    const float* A;
    const float* B;
    if (MODE == 3) {
        A = Ag + (long)z * SEQ * SEQ;
        B = Bg + (long)z * SEQ * HEAD_DIM;
    } else {
        A = Ag;
        B = Bg;
    }

    const u32 aH = smem_u32(sAh), aL = smem_u32(sAl);
    const u32 bH = smem_u32(sBh), bL = smem_u32(sBl);

    float acc[MT][4][4];
#pragma unroll
    for (int i = 0; i < MT; i++)
#pragma unroll
        for (int j = 0; j < 4; j++)
#pragma unroll
            for (int e = 0; e < 4; e++) acc[i][j][e] = 0.f;

    const int nchunks = KDIM >> 5;
    for (int c = 0; c < nchunks; c++) {
#pragma unroll
        for (int g = 0; g < 4; g++) {
            int id = tid + g * 256;
            int row = id >> 3, q = id & 7;
            float4 v = *(const float4*)(A + (long)(m0 + row) * KDIM + c * 32 + q * 4);
            __nv_bfloat16 h0, h1, h2, h3, l0, l1, l2, l3;
            cvt_split(v.x, h0, l0); cvt_split(v.y, h1, l1);
            cvt_split(v.z, h2, l2); cvt_split(v.w, h3, l3);
            *(uint2*)&sAh[row * LDT + q * 4] = make_uint2(pack_bf2(h0, h1), pack_bf2(h2, h3));
            *(uint2*)&sAl[row * LDT + q * 4] = make_uint2(pack_bf2(l0, l1), pack_bf2(l2, l3));
        }
        if (MODE == 3) {
#pragma unroll
            for (int g = 0; g < 2; g++) {
                int id = tid + g * 256;
                int k = id >> 4, nq = id & 15;
                float4 v = *(const float4*)(B + (long)(c * 32 + k) * HEAD_DIM + nq * 4);
                float xs[4] = {v.x, v.y, v.z, v.w};
#pragma unroll
                for (int e = 0; e < 4; e++) {
                    __nv_bfloat16 h, l;
                    cvt_split(xs[e], h, l);
                    int n = nq * 4 + e;
                    sBh[n * LDT + k] = h;
                    sBl[n * LDT + k] = l;
                }
            }
        } else {
#pragma unroll
            for (int g = 0; g < 4; g++) {
                int id = tid + g * 256;
                int row = id >> 3, q = id & 7;
                float4 v = *(const float4*)(B + (long)(n0 + row) * KDIM + c * 32 + q * 4);
                __nv_bfloat16 h0, h1, h2, h3, l0, l1, l2, l3;
                cvt_split(v.x, h0, l0); cvt_split(v.y, h1, l1);
                cvt_split(v.z, h2, l2); cvt_split(v.w, h3, l3);
                *(uint2*)&sBh[row * LDT + q * 4] = make_uint2(pack_bf2(h0, h1), pack_bf2(h2, h3));
                *(uint2*)&sBl[row * LDT + q * 4] = make_uint2(pack_bf2(l0, l1), pack_bf2(l2, l3));
            }
        }
        __syncthreads();

#pragma unroll
        for (int ks = 0; ks < 2; ks++) {
            const int k0 = ks * 16;
            u32 ah[MT][4], al[MT][4], bh[4][2], bl[4][2];
#pragma unroll
            for (int mt = 0; mt < MT; mt++) {
                u32 off = (u32)(((wm0 + mt * 16 + (lane & 15)) * LDT
                                 + k0 + (lane >> 4) * 8) * 2);
                ldsm4(ah[mt][0], ah[mt][1], ah[mt][2], ah[mt][3], aH + off);
                ldsm4(al[mt][0], al[mt][1], al[mt][2], al[mt][3], aL + off);
            }
#pragma unroll
            for (int np = 0; np < 2; np++) {
                u32 off = (u32)(((wn0 + np * 16 + (lane & 7) + ((lane >> 4) << 3)) * LDT
                                 + k0 + ((lane >> 3) & 1) * 8) * 2);
                u32 r0, r1, r2, r3;
                ldsm4(r0, r1, r2, r3, bH + off);
                bh[2 * np][0] = r0; bh[2 * np][1] = r1;
                bh[2 * np + 1][0] = r2; bh[2 * np + 1][1] = r3;
                ldsm4(r0, r1, r2, r3, bL + off);
                bl[2 * np][0] = r0; bl[2 * np][1] = r1;
                bl[2 * np + 1][0] = r2; bl[2 * np + 1][1] = r3;
            }
#pragma unroll
            for (int mt = 0; mt < MT; mt++)
#pragma unroll
                for (int nt = 0; nt < 4; nt++)
                    mma_bf16(acc[mt][nt], ah[mt][0], ah[mt][1], ah[mt][2], ah[mt][3],
                             bh[nt][0], bh[nt][1]);
#pragma unroll
            for (int mt = 0; mt < MT; mt++)
#pragma unroll
                for (int nt = 0; nt < 4; nt++)
                    mma_bf16(acc[mt][nt], ah[mt][0], ah[mt][1], ah[mt][2], ah[mt][3],
                             bl[nt][0], bl[nt][1]);
#pragma unroll
            for (int mt = 0; mt < MT; mt++)
#pragma unroll
                for (int nt = 0; nt < 4; nt++)
                    mma_bf16(acc[mt][nt], al[mt][0], al[mt][1], al[mt][2], al[mt][3],
                             bh[nt][0], bh[nt][1]);
        }
        __syncthreads();
    }

    const int r_lo = lane >> 2;
    const int cp = (lane & 3) * 2;
#pragma unroll
    for (int mt = 0; mt < MT; mt++) {
#pragma unroll
        for (int nt = 0; nt < 4; nt++) {
            const int n = n0 + wn0 + nt * 8 + cp;
#pragma unroll
            for (int half = 0; half < 2; half++) {
                const int m = m0 + wm0 + mt * 16 + r_lo + half * 8;
                float c0 = acc[mt][nt][half * 2];
                float c1 = acc[mt][nt][half * 2 + 1];
                float* dst;
                if (MODE == 1) {
                    c0 += bias[n]; c1 += bias[n + 1];
                    dst = Cg + (long)m * MODEL_DIM + n;
                } else {
                    int b = z / N_HEAD, h = z % N_HEAD;
                    dst = Cg + ((long)(b * SEQ + m)) * MODEL_DIM + h * HEAD_DIM + n;
                }
                *(float2*)dst = make_float2(c0, c1);
            }
        }
    }
}

// ============================================================
// Merged QKV projection: z selects (q,wq)/(k,wk)/(v,wv).
// Identical math to round-4 MODE 0; KDIM = 768.
// ============================================================
__global__ void __launch_bounds__(256)
qkv_gemm(const float* __restrict__ A0, const float* __restrict__ A1, const float* __restrict__ A2,
         const float* __restrict__ W0, const float* __restrict__ W1, const float* __restrict__ W2,
         const float* __restrict__ b0, const float* __restrict__ b1, const float* __restrict__ b2,
         float* __restrict__ C0, float* __restrict__ C1, float* __restrict__ C2)
{
    __shared__ __align__(16) __nv_bfloat16 sAh[128 * LDT];
    __shared__ __align__(16) __nv_bfloat16 sAl[128 * LDT];
    __shared__ __align__(16) __nv_bfloat16 sBh[128 * LDT];
    __shared__ __align__(16) __nv_bfloat16 sBl[128 * LDT];

    const int tid = threadIdx.x;
    const int wid = tid >> 5;
    const int lane = tid & 31;
    const int m0 = blockIdx.x * 128;
    const int n0 = blockIdx.y * 128;
    const int z = blockIdx.z;

    const float* A    = (z == 0) ? A0 : (z == 1) ? A1 : A2;
    const float* W    = (z == 0) ? W0 : (z == 1) ? W1 : W2;
    const float* bias = (z == 0) ? b0 : (z == 1) ? b1 : b2;
    float* Cg         = (z == 0) ? C0 : (z == 1) ? C1 : C2;

    const int warp_m = wid >> 2, warp_n = wid & 3;
    const int wm0 = warp_m * 64, wn0 = warp_n * 32;

    const u32 aH = smem_u32(sAh), aL = smem_u32(sAl);
    const u32 bH = smem_u32(sBh), bL = smem_u32(sBl);

    float acc[4][4][4];
#pragma unroll
    for (int i = 0; i < 4; i++)
#pragma unroll
        for (int j = 0; j < 4; j++)
#pragma unroll
            for (int e = 0; e < 4; e++) acc[i][j][e] = 0.f;

    for (int c = 0; c < (MODEL_DIM >> 5); c++) {
#pragma unroll
        for (int g = 0; g < 4; g++) {
            int id = tid + g * 256;
            int row = id >> 3, q = id & 7;
            float4 v = *(const float4*)(A + (long)(m0 + row) * MODEL_DIM + c * 32 + q * 4);
            __nv_bfloat16 h0, h1, h2, h3, l0, l1, l2, l3;
            cvt_split(v.x, h0, l0); cvt_split(v.y, h1, l1);
            cvt_split(v.z, h2, l2); cvt_split(v.w, h3, l3);
            *(uint2*)&sAh[row * LDT + q * 4] = make_uint2(pack_bf2(h0, h1), pack_bf2(h2, h3));
            *(uint2*)&sAl[row * LDT + q * 4] = make_uint2(pack_bf2(l0, l1), pack_bf2(l2, l3));
            float4 w = *(const float4*)(W + (long)(n0 + row) * MODEL_DIM + c * 32 + q * 4);
            cvt_split(w.x, h0, l0); cvt_split(w.y, h1, l1);
            cvt_split(w.z, h2, l2); cvt_split(w.w, h3, l3);
            *(uint2*)&sBh[row * LDT + q * 4] = make_uint2(pack_bf2(h0, h1), pack_bf2(h2, h3));
            *(uint2*)&sBl[row * LDT + q * 4] = make_uint2(pack_bf2(l0, l1), pack_bf2(l2, l3));
        }
        __syncthreads();

#pragma unroll
        for (int ks = 0; ks < 2; ks++) {
            const int k0 = ks * 16;
            u32 ah[4][4], al[4][4], bh[4][2], bl[4][2];
#pragma unroll
            for (int mt = 0; mt < 4; mt++) {
                u32 off = (u32)(((wm0 + mt * 16 + (lane & 15)) * LDT
                                 + k0 + (lane >> 4) * 8) * 2);
                ldsm4(ah[mt][0], ah[mt][1], ah[mt][2], ah[mt][3], aH + off);
                ldsm4(al[mt][0], al[mt][1], al[mt][2], al[mt][3], aL + off);
            }
#pragma unroll
            for (int np = 0; np < 2; np++) {
                u32 off = (u32)(((wn0 + np * 16 + (lane & 7) + ((lane >> 4) << 3)) * LDT
                                 + k0 + ((lane >> 3) & 1) * 8) * 2);
                u32 r0, r1, r2, r3;
                ldsm4(r0, r1, r2, r3, bH + off);
                bh[2 * np][0] = r0; bh[2 * np][1] = r1;
                bh[2 * np + 1][0] = r2; bh[2 * np + 1][1] = r3;
                ldsm4(r0, r1, r2, r3, bL + off);
                bl[2 * np][0] = r0; bl[2 * np][1] = r1;
                bl[2 * np + 1][0] = r2; bl[2 * np + 1][1] = r3;
            }
#pragma unroll
            for (int mt = 0; mt < 4; mt++)
#pragma unroll
                for (int nt = 0; nt < 4; nt++)
                    mma_bf16(acc[mt][nt], ah[mt][0], ah[mt][1], ah[mt][2], ah[mt][3],
                             bh[nt][0], bh[nt][1]);
#pragma unroll
            for (int mt = 0; mt < 4; mt++)
#pragma unroll
                for (int nt = 0; nt < 4; nt++)
                    mma_bf16(acc[mt][nt], ah[mt][0], ah[mt][1], ah[mt][2], ah[mt][3],
                             bl[nt][0], bl[nt][1]);
#pragma unroll
            for (int mt = 0; mt < 4; mt++)
#pragma unroll
                for (int nt = 0; nt < 4; nt++)
                    mma_bf16(acc[mt][nt], al[mt][0], al[mt][1], al[mt][2], al[mt][3],
                             bh[nt][0], bh[nt][1]);
        }
        __syncthreads();
    }

    const int r_lo = lane >> 2;
    const int cp = (lane & 3) * 2;
#pragma unroll
    for (int mt = 0; mt < 4; mt++) {
#pragma unroll
        for (int nt = 0; nt < 4; nt++) {
            const int n = n0 + wn0 + nt * 8 + cp;
#pragma unroll
            for (int half = 0; half < 2; half++) {
                const int m = m0 + wm0 + mt * 16 + r_lo + half * 8;
                float c0 = acc[mt][nt][half * 2] + bias[n];
                float c1 = acc[mt][nt][half * 2 + 1] + bias[n + 1];
                int b = m >> 11, s = m & (SEQ - 1);
                int h = n >> 6, d = n & 63;
                float* dst = Cg + (((long)(b * N_HEAD + h) * SEQ) + s) * HEAD_DIM + d;
                *(float2*)dst = make_float2(c0, c1);
            }
        }
    }
}

// ============================================================
// Fused scores + softmax.
// Block = 128 query rows x all 2048 keys for one head.
// No-max softmax (|s| << 88, exp cannot overflow fp32).
// Writes unnormalized exp to P, then in-block fixup (L2-hot).
// ============================================================
#define FLDT 72
#define FS_SMEM (4 * 128 * FLDT * 2 + 2 * 8192 * 4 + 512 * 4 + 128 * 4)  /* 141824 */

__global__ void __launch_bounds__(256)
fused_scores_softmax(const float* __restrict__ Qg, const float* __restrict__ Kg,
                     float* __restrict__ P)
{
    extern __shared__ char dsm[];
    __nv_bfloat16* sQh = (__nv_bfloat16*)dsm;
    __nv_bfloat16* sQl = sQh + 128 * FLDT;
    __nv_bfloat16* sKh = sQl + 128 * FLDT;
    __nv_bfloat16* sKl = sKh + 128 * FLDT;
    float* stg   = (float*)(sKl + 128 * FLDT);   // 2 x 8192 raw fp32 K staging
    float* lpart = stg + 2 * 8192;               // [128][4]
    float* linv  = lpart + 512;                  // [128]

    const int tid = threadIdx.x;
    const int wid = tid >> 5;
    const int lane = tid & 31;
    const int m0 = blockIdx.x * 128;
    const int bh = blockIdx.y;

    const float* Q = Qg + ((long)bh * SEQ + m0) * HEAD_DIM;
    const float* K = Kg + (long)bh * SEQ * HEAD_DIM;
    float* Pb = P + ((long)bh * SEQ + m0) * SEQ;

    for (int i = tid; i < 512; i += 256) lpart[i] = 0.f;

    // ---- Q tile 128x64: load fp32 once, split hi/lo bf16 ----
#pragma unroll
    for (int g = 0; g < 8; g++) {
        int fid = tid + g * 256;          // 0..2047
        int row = fid >> 4, q = fid & 15;
        float4 v = *(const float4*)(Q + row * HEAD_DIM + q * 4);
        __nv_bfloat16 h0, h1, h2, h3, l0, l1, l2, l3;
        cvt_split(v.x, h0, l0); cvt_split(v.y, h1, l1);
        cvt_split(v.z, h2, l2); cvt_split(v.w, h3, l3);
        *(uint2*)&sQh[row * FLDT + q * 4] = make_uint2(pack_bf2(h0, h1), pack_bf2(h2, h3));
        *(uint2*)&sQl[row * FLDT + q * 4] = make_uint2(pack_bf2(l0, l1), pack_bf2(l2, l3));
    }

    const u32 stgB = smem_u32(stg);
    // ---- prefetch K chunk 0 ----
#pragma unroll
    for (int g = 0; g < 8; g++) {
        int fid = tid + g * 256;
        CP_ASYNC16(stgB + fid * 16, K + fid * 4);
    }
    CP_COMMIT();

    const int warp_m = wid >> 2, warp_n = wid & 3;
    const int wm0 = warp_m * 64, wn0 = warp_n * 32;
    const u32 aH = smem_u32(sQh), aL = smem_u32(sQl);
    const u32 bH = smem_u32(sKh), bL = smem_u32(sKl);
    const int r_lo = lane >> 2, cp2 = (lane & 3) * 2;

    for (int c = 0; c < 16; c++) {
        if (c < 15) {
            const float* src = K + (long)(c + 1) * 8192;
            u32 dst = stgB + ((c + 1) & 1) * 32768;
#pragma unroll
            for (int g = 0; g < 8; g++) {
                int fid = tid + g * 256;
                CP_ASYNC16(dst + fid * 16, src + fid * 4);
            }
            CP_COMMIT();
            CP_WAIT1();
        } else {
            CP_WAIT0();
        }
        __syncthreads();

        // ---- convert staged K chunk -> split bf16 ----
        {
            const float* sb = stg + (c & 1) * 8192;
#pragma unroll
            for (int g = 0; g < 8; g++) {
                int fid = tid + g * 256;
                int row = fid >> 4, q = fid & 15;
                float4 v = *(const float4*)(sb + row * 64 + q * 4);
                __nv_bfloat16 h0, h1, h2, h3, l0, l1, l2, l3;
                cvt_split(v.x, h0, l0); cvt_split(v.y, h1, l1);
                cvt_split(v.z, h2, l2); cvt_split(v.w, h3, l3);
                *(uint2*)&sKh[row * FLDT + q * 4] = make_uint2(pack_bf2(h0, h1), pack_bf2(h2, h3));
                *(uint2*)&sKl[row * FLDT + q * 4] = make_uint2(pack_bf2(l0, l1), pack_bf2(l2, l3));
            }
        }
        __syncthreads();

        // ---- S = Q @ K^T for this 128x128 chunk ----
        float acc[4][4][4];
#pragma unroll
        for (int i = 0; i < 4; i++)
#pragma unroll
            for (int j = 0; j < 4; j++)
#pragma unroll
                for (int e = 0; e < 4; e++) acc[i][j][e] = 0.f;

#pragma unroll
        for (int ks = 0; ks < 4; ks++) {
            const int k0 = ks * 16;
            u32 ah[4][4], al[4][4], bh[4][2], bl[4][2];
#pragma unroll
            for (int mt = 0; mt < 4; mt++) {
                u32 off = (u32)(((wm0 + mt * 16 + (lane & 15)) * FLDT
                                 + k0 + (lane >> 4) * 8) * 2);
                ldsm4(ah[mt][0], ah[mt][1], ah[mt][2], ah[mt][3], aH + off);
                ldsm4(al[mt][0], al[mt][1], al[mt][2], al[mt][3], aL + off);
            }
#pragma unroll
            for (int np = 0; np < 2; np++) {
                u32 off = (u32)(((wn0 + np * 16 + (lane & 7) + ((lane >> 4) << 3)) * FLDT
                                 + k0 + ((lane >> 3) & 1) * 8) * 2);
                u32 r0, r1, r2, r3;
                ldsm4(r0, r1, r2, r3, bH + off);
                bh[2 * np][0] = r0; bh[2 * np][1] = r1;
                bh[2 * np + 1][0] = r2; bh[2 * np + 1][1] = r3;
                ldsm4(r0, r1, r2, r3, bL + off);
                bl[2 * np][0] = r0; bl[2 * np][1] = r1;
                bl[2 * np + 1][0] = r2; bl[2 * np + 1][1] = r3;
            }
#pragma unroll
            for (int mt = 0; mt < 4; mt++)
#pragma unroll
                for (int nt = 0; nt < 4; nt++)
                    mma_bf16(acc[mt][nt], ah[mt][0], ah[mt][1], ah[mt][2], ah[mt][3],
                             bh[nt][0], bh[nt][1]);
#pragma unroll
            for (int mt = 0; mt < 4; mt++)
#pragma unroll
                for (int nt = 0; nt < 4; nt++)
                    mma_bf16(acc[mt][nt], ah[mt][0], ah[mt][1], ah[mt][2], ah[mt][3],
                             bl[nt][0], bl[nt][1]);
#pragma unroll
            for (int mt = 0; mt < 4; mt++)
#pragma unroll
                for (int nt = 0; nt < 4; nt++)
                    mma_bf16(acc[mt][nt], al[mt][0], al[mt][1], al[mt][2], al[mt][3],
                             bh[nt][0], bh[nt][1]);
        }

        // ---- exp, row-sum accumulation, store unnormalized P ----
#pragma unroll
        for (int mt = 0; mt < 4; mt++) {
#pragma unroll
            for (int half = 0; half < 2; half++) {
                const int row = wm0 + mt * 16 + r_lo + half * 8;
                float rs = 0.f;
#pragma unroll
                for (int nt = 0; nt < 4; nt++) {
                    float e0 = fast_exp(acc[mt][nt][half * 2]     * 0.125f);
                    float e1 = fast_exp(acc[mt][nt][half * 2 + 1] * 0.125f);
                    rs += e0 + e1;
                    const int n = c * 128 + wn0 + nt * 8 + cp2;
                    *(float2*)(Pb + (long)row * SEQ + n) = make_float2(e0, e1);
                }
                rs += __shfl_xor_sync(0xffffffffu, rs, 1);
                rs += __shfl_xor_sync(0xffffffffu, rs, 2);
                if ((lane & 3) == 0) lpart[row * 4 + warp_n] += rs;
            }
        }
    }

    __syncthreads();
    if (tid < 128)
        linv[tid] = 1.f / (lpart[tid * 4] + lpart[tid * 4 + 1] +
                           lpart[tid * 4 + 2] + lpart[tid * 4 + 3]);
    __syncthreads();

    // ---- fixup: normalize the block's contiguous 128x2048 P region ----
    float4* p4 = (float4*)Pb;
#pragma unroll 4
    for (int idx = tid; idx < 128 * 512; idx += 256) {
        float inv = linv[idx >> 9];
        float4 v = p4[idx];
        v.x *= inv; v.y *= inv; v.z *= inv; v.w *= inv;
        p4[idx] = v;
    }
}

// ============================================================
// Host launch
// ============================================================
extern "C" void kernel_launch(void* const* d_in, const int* in_sizes, int n_in,
                              void* d_out, int out_size)
{
    const float* q    = (const float*)d_in[0];
    const float* k    = (const float*)d_in[1];
    const float* v    = (const float*)d_in[2];
    const float* wq_w = (const float*)d_in[3];
    const float* wq_b = (const float*)d_in[4];
    const float* wk_w = (const float*)d_in[5];
    const float* wk_b = (const float*)d_in[6];
    const float* wv_w = (const float*)d_in[7];
    const float* wv_b = (const float*)d_in[8];
    const float* wo_w = (const float*)d_in[9];
    const float* wo_b = (const float*)d_in[10];
    float* out = (float*)d_out;

    float *qh, *kh, *vh, *ctx;
    cudaGetSymbolAddress((void**)&qh, g_qh);
    cudaGetSymbolAddress((void**)&kh, g_kh);
    cudaGetSymbolAddress((void**)&vh, g_vh);
    cudaGetSymbolAddress((void**)&ctx, g_ctx);

    float* attnW = out + (long)M_TOT * MODEL_DIM;

    cudaFuncSetAttribute(fused_scores_softmax,
                         cudaFuncAttributeMaxDynamicSharedMemorySize, FS_SMEM);

    dim3 gqkv(M_TOT / 128, MODEL_DIM / 128, 3);           // (32, 6, 3)
    qkv_gemm<<<gqkv, 256>>>(q, k, v, wq_w, wk_w, wv_w,
                            wq_b, wk_b, wv_b, qh, kh, vh);

    dim3 gfs(SEQ / 128, BHEADS);                          // (16, 24)
    fused_scores_softmax<<<gfs, 256, FS_SMEM>>>(qh, kh, attnW);

    dim3 gpv(SEQ / 128, 1, BHEADS);                       // (16, 1, 24)
    mma_gemm<3><<<gpv, 256>>>(attnW, vh, nullptr, ctx, SEQ);

    dim3 gout(M_TOT / 128, MODEL_DIM / 128, 1);           // (32, 6)
    mma_gemm<1><<<gout, 256>>>(ctx, wo_w, wo_b, out, MODEL_DIM);
}

// round 8
// speedup vs baseline: 9.6713x; 1.1148x over previous
#include <cuda_runtime.h>
#include <cuda_fp16.h>

#define MODEL_DIM 768
#define N_HEAD 12
#define HEAD_DIM 64
#define SEQ 2048
#define M_TOT 4096
#define BHEADS 24

typedef unsigned int u32;

// -------- device scratch (no allocations allowed) --------
__device__ float g_qh[BHEADS * SEQ * HEAD_DIM];
__device__ float g_kh[BHEADS * SEQ * HEAD_DIM];
__device__ float g_vh[BHEADS * SEQ * HEAD_DIM];
__device__ float g_ctx[M_TOT * MODEL_DIM];

// ============================================================
// helpers
// ============================================================
__device__ __forceinline__ u32 smem_u32(const void* p) {
    u32 a;
    asm("{ .reg .u64 t; cvta.to.shared.u64 t, %1; cvt.u32.u64 %0, t; }"
        : "=r"(a) : "l"(p));
    return a;
}

__device__ __forceinline__ void ldsm4(u32& r0, u32& r1, u32& r2, u32& r3, u32 addr) {
    asm volatile("ldmatrix.sync.aligned.m8n8.x4.shared.b16 {%0,%1,%2,%3}, [%4];"
        : "=r"(r0), "=r"(r1), "=r"(r2), "=r"(r3) : "r"(addr));
}

__device__ __forceinline__ void mma_f16(float* c, u32 a0, u32 a1, u32 a2, u32 a3,
                                        u32 b0, u32 b1) {
    asm volatile(
        "mma.sync.aligned.m16n8k16.row.col.f32.f16.f16.f32 "
        "{%0,%1,%2,%3}, {%4,%5,%6,%7}, {%8,%9}, {%0,%1,%2,%3};"
        : "+f"(c[0]), "+f"(c[1]), "+f"(c[2]), "+f"(c[3])
        : "r"(a0), "r"(a1), "r"(a2), "r"(a3), "r"(b0), "r"(b1));
}

#define CP_ASYNC16(d, s) asm volatile("cp.async.cg.shared.global [%0], [%1], 16;" :: "r"(d), "l"(s) : "memory")
#define CP_COMMIT()      asm volatile("cp.async.commit_group;" ::: "memory")
#define CP_WAIT1()       asm volatile("cp.async.wait_group 1;" ::: "memory")
#define CP_WAIT0()       asm volatile("cp.async.wait_group 0;" ::: "memory")

__device__ __forceinline__ u32 pack_h2(__half a, __half b) {
    __half2 p(a, b);
    return *reinterpret_cast<u32*>(&p);
}

__device__ __forceinline__ void cvt_split(float x, __half& h, __half& l) {
    h = __float2half_rn(x);
    l = __float2half_rn(x - __half2float(h));
}

__device__ __forceinline__ float fast_exp(float x)
{
    const float L2E = 1.4426950408889634f;
    float t = fmaf(x, L2E, 12582912.0f);
    int e = __float_as_int(t) - 0x4B400000;
    float fi = t - 12582912.0f;
    float f = fmaf(x, L2E, -fi);
    float p = 1.53953850e-4f;
    p = fmaf(p, f, 1.33335581e-3f);
    p = fmaf(p, f, 9.61812911e-3f);
    p = fmaf(p, f, 5.55041087e-2f);
    p = fmaf(p, f, 2.40226507e-1f);
    p = fmaf(p, f, 6.93147181e-1f);
    p = fmaf(p, f, 1.0f);
    return __int_as_float(__float_as_int(p) + (e << 23));
}

#define LDT 40   /* smem tile stride in halves (80B rows, 16B-mult: ldmatrix OK) */

// ============================================================
// 2-term fp16 GEMM with register-prefetch double buffering.
//   C = A @ B^T ≈ Ah@Bh^T + Ah@Bl^T   (fp32 accum)
// MODE 1: plain + bias       (output projection)
// MODE 3: PV (B = V [K,64], transposed on load), batched per head
// ============================================================
template <int MODE>
__global__ void __launch_bounds__(256, 2)
mma_gemm(const float* __restrict__ Ag, const float* __restrict__ Bg,
         const float* __restrict__ bias, float* __restrict__ Cg, int KDIM)
{
    constexpr int BN = (MODE == 3) ? 64 : 128;
    constexpr int MT = (MODE == 3) ? 2 : 4;
    constexpr int WM = (MODE == 3) ? 32 : 64;
    constexpr int ABUF = 128 * LDT;            // halves per A buffer
    constexpr int BBUF = BN * LDT;
    constexpr int NB = (MODE == 3) ? 2 : 4;    // B prefetch float4s / thread

    extern __shared__ __half hsm[];
    __half* sAh = hsm;                         // [2][ABUF]
    __half* sBh = sAh + 2 * ABUF;              // [2][BBUF]
    __half* sBl = sBh + 2 * BBUF;              // [2][BBUF]

    const int tid = threadIdx.x;
    const int wid = tid >> 5;
    const int lane = tid & 31;
    const int m0 = blockIdx.x * 128;
    const int n0 = blockIdx.y * BN;
    const int z = blockIdx.z;

    const int warp_m = (MODE == 3) ? (wid >> 1) : (wid >> 2);
    const int warp_n = (MODE == 3) ? (wid & 1) : (wid & 3);
    const int wm0 = warp_m * WM;
    const int wn0 = warp_n * 32;

    const float* A;
    const float* B;
    if (MODE == 3) {
        A = Ag + (long)z * SEQ * SEQ;
        B = Bg + (long)z * SEQ * HEAD_DIM;
    } else {
        A = Ag;
        B = Bg;
    }

    float acc[MT][4][4];
#pragma unroll
    for (int i = 0; i < MT; i++)
#pragma unroll
        for (int j = 0; j < 4; j++)
#pragma unroll
            for (int e = 0; e < 4; e++) acc[i][j][e] = 0.f;

    float4 av[4], bv[NB];

    // ---- LDG helpers (inlined via macros of loops) ----
    auto ldgA = [&](int c) {
#pragma unroll
        for (int g = 0; g < 4; g++) {
            int id = tid + g * 256;
            int row = id >> 3, q = id & 7;
            av[g] = *(const float4*)(A + (long)(m0 + row) * KDIM + c * 32 + q * 4);
        }
    };
    auto ldgB = [&](int c) {
        if (MODE == 3) {
#pragma unroll
            for (int g = 0; g < NB; g++) {
                int id = tid + g * 256;
                int k = id >> 4, nq = id & 15;
                bv[g] = *(const float4*)(B + (long)(c * 32 + k) * HEAD_DIM + nq * 4);
            }
        } else {
#pragma unroll
            for (int g = 0; g < NB; g++) {
                int id = tid + g * 256;
                int row = id >> 3, q = id & 7;
                bv[g] = *(const float4*)(B + (long)(n0 + row) * KDIM + c * 32 + q * 4);
            }
        }
    };
    auto sts = [&](int bu) {
        __half* dAh = sAh + bu * ABUF;
        __half* dBh = sBh + bu * BBUF;
        __half* dBl = sBl + bu * BBUF;
#pragma unroll
        for (int g = 0; g < 4; g++) {
            int id = tid + g * 256;
            int row = id >> 3, q = id & 7;
            __half h0 = __float2half_rn(av[g].x), h1 = __float2half_rn(av[g].y);
            __half h2 = __float2half_rn(av[g].z), h3 = __float2half_rn(av[g].w);
            *(uint2*)&dAh[row * LDT + q * 4] = make_uint2(pack_h2(h0, h1), pack_h2(h2, h3));
        }
        if (MODE == 3) {
#pragma unroll
            for (int g = 0; g < NB; g++) {
                int id = tid + g * 256;
                int k = id >> 4, nq = id & 15;
                float xs[4] = {bv[g].x, bv[g].y, bv[g].z, bv[g].w};
#pragma unroll
                for (int e = 0; e < 4; e++) {
                    __half h, l;
                    cvt_split(xs[e], h, l);
                    int n = nq * 4 + e;
                    dBh[n * LDT + k] = h;
                    dBl[n * LDT + k] = l;
                }
            }
        } else {
#pragma unroll
            for (int g = 0; g < NB; g++) {
                int id = tid + g * 256;
                int row = id >> 3, q = id & 7;
                __half h0, h1, h2, h3, l0, l1, l2, l3;
                cvt_split(bv[g].x, h0, l0); cvt_split(bv[g].y, h1, l1);
                cvt_split(bv[g].z, h2, l2); cvt_split(bv[g].w, h3, l3);
                *(uint2*)&dBh[row * LDT + q * 4] = make_uint2(pack_h2(h0, h1), pack_h2(h2, h3));
                *(uint2*)&dBl[row * LDT + q * 4] = make_uint2(pack_h2(l0, l1), pack_h2(l2, l3));
            }
        }
    };

    const int nchunks = KDIM >> 5;
    ldgA(0); ldgB(0); sts(0);

    for (int c = 0; c < nchunks; c++) {
        if (c + 1 < nchunks) { ldgA(c + 1); ldgB(c + 1); }
        __syncthreads();

        const int bu = c & 1;
        const u32 aH = smem_u32(sAh + bu * ABUF);
        const u32 bH = smem_u32(sBh + bu * BBUF);
        const u32 bL = smem_u32(sBl + bu * BBUF);
#pragma unroll
        for (int ks = 0; ks < 2; ks++) {
            const int k0 = ks * 16;
            u32 ah[MT][4], bh[4][2], bl[4][2];
#pragma unroll
            for (int mt = 0; mt < MT; mt++) {
                u32 off = (u32)(((wm0 + mt * 16 + (lane & 15)) * LDT
                                 + k0 + (lane >> 4) * 8) * 2);
                ldsm4(ah[mt][0], ah[mt][1], ah[mt][2], ah[mt][3], aH + off);
            }
#pragma unroll
            for (int np = 0; np < 2; np++) {
                u32 off = (u32)(((wn0 + np * 16 + (lane & 7) + ((lane >> 4) << 3)) * LDT
                                 + k0 + ((lane >> 3) & 1) * 8) * 2);
                u32 r0, r1, r2, r3;
                ldsm4(r0, r1, r2, r3, bH + off);
                bh[2 * np][0] = r0; bh[2 * np][1] = r1;
                bh[2 * np + 1][0] = r2; bh[2 * np + 1][1] = r3;
                ldsm4(r0, r1, r2, r3, bL + off);
                bl[2 * np][0] = r0; bl[2 * np][1] = r1;
                bl[2 * np + 1][0] = r2; bl[2 * np + 1][1] = r3;
            }
#pragma unroll
            for (int mt = 0; mt < MT; mt++)
#pragma unroll
                for (int nt = 0; nt < 4; nt++)
                    mma_f16(acc[mt][nt], ah[mt][0], ah[mt][1], ah[mt][2], ah[mt][3],
                            bh[nt][0], bh[nt][1]);
#pragma unroll
            for (int mt = 0; mt < MT; mt++)
#pragma unroll
                for (int nt = 0; nt < 4; nt++)
                    mma_f16(acc[mt][nt], ah[mt][0], ah[mt][1], ah[mt][2], ah[mt][3],
                            bl[nt][0], bl[nt][1]);
        }
        if (c + 1 < nchunks) sts((c + 1) & 1);
    }

    // ---- epilogue ----
    const int r_lo = lane >> 2;
    const int cp = (lane & 3) * 2;
#pragma unroll
    for (int mt = 0; mt < MT; mt++) {
#pragma unroll
        for (int nt = 0; nt < 4; nt++) {
            const int n = n0 + wn0 + nt * 8 + cp;
#pragma unroll
            for (int half = 0; half < 2; half++) {
                const int m = m0 + wm0 + mt * 16 + r_lo + half * 8;
                float c0 = acc[mt][nt][half * 2];
                float c1 = acc[mt][nt][half * 2 + 1];
                float* dst;
                if (MODE == 1) {
                    c0 += bias[n]; c1 += bias[n + 1];
                    dst = Cg + (long)m * MODEL_DIM + n;
                } else {
                    int b = z / N_HEAD, h = z % N_HEAD;
                    dst = Cg + ((long)(b * SEQ + m)) * MODEL_DIM + h * HEAD_DIM + n;
                }
                *(float2*)dst = make_float2(c0, c1);
            }
        }
    }
}

// ============================================================
// Merged QKV projection (3-term fp16, round-5 structure).
// ============================================================
__global__ void __launch_bounds__(256)
qkv_gemm(const float* __restrict__ A0, const float* __restrict__ A1, const float* __restrict__ A2,
         const float* __restrict__ W0, const float* __restrict__ W1, const float* __restrict__ W2,
         const float* __restrict__ b0, const float* __restrict__ b1, const float* __restrict__ b2,
         float* __restrict__ C0, float* __restrict__ C1, float* __restrict__ C2)
{
    __shared__ __align__(16) __half sAh[128 * LDT];
    __shared__ __align__(16) __half sAl[128 * LDT];
    __shared__ __align__(16) __half sBh[128 * LDT];
    __shared__ __align__(16) __half sBl[128 * LDT];

    const int tid = threadIdx.x;
    const int wid = tid >> 5;
    const int lane = tid & 31;
    const int m0 = blockIdx.x * 128;
    const int n0 = blockIdx.y * 128;
    const int z = blockIdx.z;

    const float* A    = (z == 0) ? A0 : (z == 1) ? A1 : A2;
    const float* W    = (z == 0) ? W0 : (z == 1) ? W1 : W2;
    const float* bias = (z == 0) ? b0 : (z == 1) ? b1 : b2;
    float* Cg         = (z == 0) ? C0 : (z == 1) ? C1 : C2;

    const int warp_m = wid >> 2, warp_n = wid & 3;
    const int wm0 = warp_m * 64, wn0 = warp_n * 32;

    const u32 aH = smem_u32(sAh), aL = smem_u32(sAl);
    const u32 bH = smem_u32(sBh), bL = smem_u32(sBl);

    float acc[4][4][4];
#pragma unroll
    for (int i = 0; i < 4; i++)
#pragma unroll
        for (int j = 0; j < 4; j++)
#pragma unroll
            for (int e = 0; e < 4; e++) acc[i][j][e] = 0.f;

    for (int c = 0; c < (MODEL_DIM >> 5); c++) {
#pragma unroll
        for (int g = 0; g < 4; g++) {
            int id = tid + g * 256;
            int row = id >> 3, q = id & 7;
            float4 v = *(const float4*)(A + (long)(m0 + row) * MODEL_DIM + c * 32 + q * 4);
            __half h0, h1, h2, h3, l0, l1, l2, l3;
            cvt_split(v.x, h0, l0); cvt_split(v.y, h1, l1);
            cvt_split(v.z, h2, l2); cvt_split(v.w, h3, l3);
            *(uint2*)&sAh[row * LDT + q * 4] = make_uint2(pack_h2(h0, h1), pack_h2(h2, h3));
            *(uint2*)&sAl[row * LDT + q * 4] = make_uint2(pack_h2(l0, l1), pack_h2(l2, l3));
            float4 w = *(const float4*)(W + (long)(n0 + row) * MODEL_DIM + c * 32 + q * 4);
            cvt_split(w.x, h0, l0); cvt_split(w.y, h1, l1);
            cvt_split(w.z, h2, l2); cvt_split(w.w, h3, l3);
            *(uint2*)&sBh[row * LDT + q * 4] = make_uint2(pack_h2(h0, h1), pack_h2(h2, h3));
            *(uint2*)&sBl[row * LDT + q * 4] = make_uint2(pack_h2(l0, l1), pack_h2(l2, l3));
        }
        __syncthreads();

#pragma unroll
        for (int ks = 0; ks < 2; ks++) {
            const int k0 = ks * 16;
            u32 ah[4][4], al[4][4], bh[4][2], bl[4][2];
#pragma unroll
            for (int mt = 0; mt < 4; mt++) {
                u32 off = (u32)(((wm0 + mt * 16 + (lane & 15)) * LDT
                                 + k0 + (lane >> 4) * 8) * 2);
                ldsm4(ah[mt][0], ah[mt][1], ah[mt][2], ah[mt][3], aH + off);
                ldsm4(al[mt][0], al[mt][1], al[mt][2], al[mt][3], aL + off);
            }
#pragma unroll
            for (int np = 0; np < 2; np++) {
                u32 off = (u32)(((wn0 + np * 16 + (lane & 7) + ((lane >> 4) << 3)) * LDT
                                 + k0 + ((lane >> 3) & 1) * 8) * 2);
                u32 r0, r1, r2, r3;
                ldsm4(r0, r1, r2, r3, bH + off);
                bh[2 * np][0] = r0; bh[2 * np][1] = r1;
                bh[2 * np + 1][0] = r2; bh[2 * np + 1][1] = r3;
                ldsm4(r0, r1, r2, r3, bL + off);
                bl[2 * np][0] = r0; bl[2 * np][1] = r1;
                bl[2 * np + 1][0] = r2; bl[2 * np + 1][1] = r3;
            }
#pragma unroll
            for (int mt = 0; mt < 4; mt++)
#pragma unroll
                for (int nt = 0; nt < 4; nt++)
                    mma_f16(acc[mt][nt], ah[mt][0], ah[mt][1], ah[mt][2], ah[mt][3],
                            bh[nt][0], bh[nt][1]);
#pragma unroll
            for (int mt = 0; mt < 4; mt++)
#pragma unroll
                for (int nt = 0; nt < 4; nt++)
                    mma_f16(acc[mt][nt], ah[mt][0], ah[mt][1], ah[mt][2], ah[mt][3],
                            bl[nt][0], bl[nt][1]);
#pragma unroll
            for (int mt = 0; mt < 4; mt++)
#pragma unroll
                for (int nt = 0; nt < 4; nt++)
                    mma_f16(acc[mt][nt], al[mt][0], al[mt][1], al[mt][2], al[mt][3],
                            bh[nt][0], bh[nt][1]);
        }
        __syncthreads();
    }

    const int r_lo = lane >> 2;
    const int cp = (lane & 3) * 2;
#pragma unroll
    for (int mt = 0; mt < 4; mt++) {
#pragma unroll
        for (int nt = 0; nt < 4; nt++) {
            const int n = n0 + wn0 + nt * 8 + cp;
#pragma unroll
            for (int half = 0; half < 2; half++) {
                const int m = m0 + wm0 + mt * 16 + r_lo + half * 8;
                float c0 = acc[mt][nt][half * 2] + bias[n];
                float c1 = acc[mt][nt][half * 2 + 1] + bias[n + 1];
                int b = m >> 11, s = m & (SEQ - 1);
                int h = n >> 6, d = n & 63;
                float* dst = Cg + (((long)(b * N_HEAD + h) * SEQ) + s) * HEAD_DIM + d;
                *(float2*)dst = make_float2(c0, c1);
            }
        }
    }
}

// ============================================================
// Fused scores + softmax (2-term fp16).
// Block = 128 query rows x all 2048 keys, one head.
// cp.async K pipe; no-max softmax; in-block L2-hot fixup.
// ============================================================
#define FLDT 72
#define FS_SMEM (2 * 8192 * 4 + 3 * 128 * FLDT * 2 + 512 * 4 + 128 * 4) /* 123392 */

__global__ void __launch_bounds__(256)
fused_scores_softmax(const float* __restrict__ Qg, const float* __restrict__ Kg,
                     float* __restrict__ P)
{
    extern __shared__ char dsm[];
    float* stg   = (float*)dsm;                       // [2][8192] raw fp32 K staging
    __half* sQh  = (__half*)(dsm + 65536);
    __half* sKh  = sQh + 128 * FLDT;
    __half* sKl  = sKh + 128 * FLDT;
    float* lpart = (float*)(dsm + 65536 + 3 * 128 * FLDT * 2);  // [128][4]
    float* linv  = lpart + 512;                                  // [128]

    const int tid = threadIdx.x;
    const int wid = tid >> 5;
    const int lane = tid & 31;
    const int m0 = blockIdx.x * 128;
    const int bh_idx = blockIdx.y;

    const float* Q = Qg + ((long)bh_idx * SEQ + m0) * HEAD_DIM;
    const float* K = Kg + (long)bh_idx * SEQ * HEAD_DIM;
    float* Pb = P + ((long)bh_idx * SEQ + m0) * SEQ;

    for (int i = tid; i < 512; i += 256) lpart[i] = 0.f;

    // ---- Q tile 128x64: hi halves only (2-term) ----
#pragma unroll
    for (int g = 0; g < 8; g++) {
        int fid = tid + g * 256;
        int row = fid >> 4, q = fid & 15;
        float4 v = *(const float4*)(Q + row * HEAD_DIM + q * 4);
        __half h0 = __float2half_rn(v.x), h1 = __float2half_rn(v.y);
        __half h2 = __float2half_rn(v.z), h3 = __float2half_rn(v.w);
        *(uint2*)&sQh[row * FLDT + q * 4] = make_uint2(pack_h2(h0, h1), pack_h2(h2, h3));
    }

    const u32 stgB = smem_u32(stg);
#pragma unroll
    for (int g = 0; g < 8; g++) {
        int fid = tid + g * 256;
        CP_ASYNC16(stgB + fid * 16, K + fid * 4);
    }
    CP_COMMIT();

    const int warp_m = wid >> 2, warp_n = wid & 3;
    const int wm0 = warp_m * 64, wn0 = warp_n * 32;
    const u32 aH = smem_u32(sQh);
    const u32 bH = smem_u32(sKh), bL = smem_u32(sKl);
    const int r_lo = lane >> 2, cp2 = (lane & 3) * 2;

    for (int c = 0; c < 16; c++) {
        if (c < 15) {
            const float* src = K + (long)(c + 1) * 8192;
            u32 dst = stgB + ((c + 1) & 1) * 32768;
#pragma unroll
            for (int g = 0; g < 8; g++) {
                int fid = tid + g * 256;
                CP_ASYNC16(dst + fid * 16, src + fid * 4);
            }
            CP_COMMIT();
            CP_WAIT1();
        } else {
            CP_WAIT0();
        }
        __syncthreads();

        // ---- convert staged K chunk -> hi/lo halves ----
        {
            const float* sb = stg + (c & 1) * 8192;
#pragma unroll
            for (int g = 0; g < 8; g++) {
                int fid = tid + g * 256;
                int row = fid >> 4, q = fid & 15;
                float4 v = *(const float4*)(sb + row * 64 + q * 4);
                __half h0, h1, h2, h3, l0, l1, l2, l3;
                cvt_split(v.x, h0, l0); cvt_split(v.y, h1, l1);
                cvt_split(v.z, h2, l2); cvt_split(v.w, h3, l3);
                *(uint2*)&sKh[row * FLDT + q * 4] = make_uint2(pack_h2(h0, h1), pack_h2(h2, h3));
                *(uint2*)&sKl[row * FLDT + q * 4] = make_uint2(pack_h2(l0, l1), pack_h2(l2, l3));
            }
        }
        __syncthreads();

        // ---- S = Q @ K^T (2-term) ----
        float acc[4][4][4];
#pragma unroll
        for (int i = 0; i < 4; i++)
#pragma unroll
            for (int j = 0; j < 4; j++)
#pragma unroll
                for (int e = 0; e < 4; e++) acc[i][j][e] = 0.f;

#pragma unroll
        for (int ks = 0; ks < 4; ks++) {
            const int k0 = ks * 16;
            u32 ah[4][4], bh[4][2], bl[4][2];
#pragma unroll
            for (int mt = 0; mt < 4; mt++) {
                u32 off = (u32)(((wm0 + mt * 16 + (lane & 15)) * FLDT
                                 + k0 + (lane >> 4) * 8) * 2);
                ldsm4(ah[mt][0], ah[mt][1], ah[mt][2], ah[mt][3], aH + off);
            }
#pragma unroll
            for (int np = 0; np < 2; np++) {
                u32 off = (u32)(((wn0 + np * 16 + (lane & 7) + ((lane >> 4) << 3)) * FLDT
                                 + k0 + ((lane >> 3) & 1) * 8) * 2);
                u32 r0, r1, r2, r3;
                ldsm4(r0, r1, r2, r3, bH + off);
                bh[2 * np][0] = r0; bh[2 * np][1] = r1;
                bh[2 * np + 1][0] = r2; bh[2 * np + 1][1] = r3;
                ldsm4(r0, r1, r2, r3, bL + off);
                bl[2 * np][0] = r0; bl[2 * np][1] = r1;
                bl[2 * np + 1][0] = r2; bl[2 * np + 1][1] = r3;
            }
#pragma unroll
            for (int mt = 0; mt < 4; mt++)
#pragma unroll
                for (int nt = 0; nt < 4; nt++)
                    mma_f16(acc[mt][nt], ah[mt][0], ah[mt][1], ah[mt][2], ah[mt][3],
                            bh[nt][0], bh[nt][1]);
#pragma unroll
            for (int mt = 0; mt < 4; mt++)
#pragma unroll
                for (int nt = 0; nt < 4; nt++)
                    mma_f16(acc[mt][nt], ah[mt][0], ah[mt][1], ah[mt][2], ah[mt][3],
                            bl[nt][0], bl[nt][1]);
        }

        // ---- exp, row-sum accumulation, store unnormalized E ----
#pragma unroll
        for (int mt = 0; mt < 4; mt++) {
#pragma unroll
            for (int half = 0; half < 2; half++) {
                const int row = wm0 + mt * 16 + r_lo + half * 8;
                float rs = 0.f;
#pragma unroll
                for (int nt = 0; nt < 4; nt++) {
                    float e0 = fast_exp(acc[mt][nt][half * 2]     * 0.125f);
                    float e1 = fast_exp(acc[mt][nt][half * 2 + 1] * 0.125f);
                    rs += e0 + e1;
                    const int n = c * 128 + wn0 + nt * 8 + cp2;
                    *(float2*)(Pb + (long)row * SEQ + n) = make_float2(e0, e1);
                }
                rs += __shfl_xor_sync(0xffffffffu, rs, 1);
                rs += __shfl_xor_sync(0xffffffffu, rs, 2);
                if ((lane & 3) == 0) lpart[row * 4 + warp_n] += rs;
            }
        }
    }

    __syncthreads();
    if (tid < 128)
        linv[tid] = 1.f / (lpart[tid * 4] + lpart[tid * 4 + 1] +
                           lpart[tid * 4 + 2] + lpart[tid * 4 + 3]);
    __syncthreads();

    // ---- fixup: normalize block's 128x2048 P region (L2-hot) ----
    float4* p4 = (float4*)Pb;
#pragma unroll 4
    for (int idx = tid; idx < 128 * 512; idx += 256) {
        float inv = linv[idx >> 9];
        float4 v = p4[idx];
        v.x *= inv; v.y *= inv; v.z *= inv; v.w *= inv;
        p4[idx] = v;
    }
}

// ============================================================
// Host launch
// ============================================================
extern "C" void kernel_launch(void* const* d_in, const int* in_sizes, int n_in,
                              void* d_out, int out_size)
{
    const float* q    = (const float*)d_in[0];
    const float* k    = (const float*)d_in[1];
    const float* v    = (const float*)d_in[2];
    const float* wq_w = (const float*)d_in[3];
    const float* wq_b = (const float*)d_in[4];
    const float* wk_w = (const float*)d_in[5];
    const float* wk_b = (const float*)d_in[6];
    const float* wv_w = (const float*)d_in[7];
    const float* wv_b = (const float*)d_in[8];
    const float* wo_w = (const float*)d_in[9];
    const float* wo_b = (const float*)d_in[10];
    float* out = (float*)d_out;

    float *qh, *kh, *vh, *ctx;
    cudaGetSymbolAddress((void**)&qh, g_qh);
    cudaGetSymbolAddress((void**)&kh, g_kh);
    cudaGetSymbolAddress((void**)&vh, g_vh);
    cudaGetSymbolAddress((void**)&ctx, g_ctx);

    float* attnW = out + (long)M_TOT * MODEL_DIM;

    const int SMEM_M1 = (2 * 128 * LDT + 4 * 128 * LDT) * 2;   // 61440 B
    const int SMEM_M3 = (2 * 128 * LDT + 4 * 64 * LDT) * 2;    // 40960 B

    cudaFuncSetAttribute(fused_scores_softmax,
                         cudaFuncAttributeMaxDynamicSharedMemorySize, FS_SMEM);
    cudaFuncSetAttribute(mma_gemm<1>,
                         cudaFuncAttributeMaxDynamicSharedMemorySize, SMEM_M1);
    cudaFuncSetAttribute(mma_gemm<3>,
                         cudaFuncAttributeMaxDynamicSharedMemorySize, SMEM_M3);

    dim3 gqkv(M_TOT / 128, MODEL_DIM / 128, 3);           // (32, 6, 3)
    qkv_gemm<<<gqkv, 256>>>(q, k, v, wq_w, wk_w, wv_w,
                            wq_b, wk_b, wv_b, qh, kh, vh);

    dim3 gfs(SEQ / 128, BHEADS);                          // (16, 24)
    fused_scores_softmax<<<gfs, 256, FS_SMEM>>>(qh, kh, attnW);

    dim3 gpv(SEQ / 128, 1, BHEADS);                       // (16, 1, 24)
    mma_gemm<3><<<gpv, 256, SMEM_M3>>>(attnW, vh, nullptr, ctx, SEQ);

    dim3 gout(M_TOT / 128, MODEL_DIM / 128, 1);           // (32, 6)
    mma_gemm<1><<<gout, 256, SMEM_M1>>>(ctx, wo_w, wo_b, out, MODEL_DIM);
}

// round 15
// speedup vs baseline: 11.4817x; 1.1872x over previous
#include <cuda_runtime.h>
#include <cuda_fp16.h>

#define MODEL_DIM 768
#define N_HEAD 12
#define HEAD_DIM 64
#define SEQ 2048
#define M_TOT 4096
#define BHEADS 24

typedef unsigned int u32;

// -------- device scratch (no allocations allowed) --------
__device__ float g_qh[BHEADS * SEQ * HEAD_DIM];
__device__ float g_kh[BHEADS * SEQ * HEAD_DIM];
__device__ float g_vh[BHEADS * SEQ * HEAD_DIM];
__device__ float g_ctx[M_TOT * MODEL_DIM];

// ============================================================
// helpers
// ============================================================
__device__ __forceinline__ u32 smem_u32(const void* p) {
    u32 a;
    asm("{ .reg .u64 t; cvta.to.shared.u64 t, %1; cvt.u32.u64 %0, t; }"
        : "=r"(a) : "l"(p));
    return a;
}

__device__ __forceinline__ void ldsm4(u32& r0, u32& r1, u32& r2, u32& r3, u32 addr) {
    asm volatile("ldmatrix.sync.aligned.m8n8.x4.shared.b16 {%0,%1,%2,%3}, [%4];"
        : "=r"(r0), "=r"(r1), "=r"(r2), "=r"(r3) : "r"(addr));
}

__device__ __forceinline__ void ldsm4t(u32& r0, u32& r1, u32& r2, u32& r3, u32 addr) {
    asm volatile("ldmatrix.sync.aligned.m8n8.x4.trans.shared.b16 {%0,%1,%2,%3}, [%4];"
        : "=r"(r0), "=r"(r1), "=r"(r2), "=r"(r3) : "r"(addr));
}

__device__ __forceinline__ void mma_f16(float* c, u32 a0, u32 a1, u32 a2, u32 a3,
                                        u32 b0, u32 b1) {
    asm volatile(
        "mma.sync.aligned.m16n8k16.row.col.f32.f16.f16.f32 "
        "{%0,%1,%2,%3}, {%4,%5,%6,%7}, {%8,%9}, {%0,%1,%2,%3};"
        : "+f"(c[0]), "+f"(c[1]), "+f"(c[2]), "+f"(c[3])
        : "r"(a0), "r"(a1), "r"(a2), "r"(a3), "r"(b0), "r"(b1));
}

#define CP_ASYNC16(d, s) asm volatile("cp.async.cg.shared.global [%0], [%1], 16;" :: "r"(d), "l"(s) : "memory")
#define CP_COMMIT()      asm volatile("cp.async.commit_group;" ::: "memory")
#define CP_WAIT1()       asm volatile("cp.async.wait_group 1;" ::: "memory")
#define CP_WAIT0()       asm volatile("cp.async.wait_group 0;" ::: "memory")

__device__ __forceinline__ u32 pack_h2(__half a, __half b) {
    __half2 p(a, b);
    return *reinterpret_cast<u32*>(&p);
}

__device__ __forceinline__ void cvt_split(float x, __half& h, __half& l) {
    h = __float2half_rn(x);
    l = __float2half_rn(x - __half2float(h));
}

__device__ __forceinline__ float fast_exp(float x)
{
    const float L2E = 1.4426950408889634f;
    float t = fmaf(x, L2E, 12582912.0f);
    int e = __float_as_int(t) - 0x4B400000;
    float fi = t - 12582912.0f;
    float f = fmaf(x, L2E, -fi);
    float p = 1.53953850e-4f;
    p = fmaf(p, f, 1.33335581e-3f);
    p = fmaf(p, f, 9.61812911e-3f);
    p = fmaf(p, f, 5.55041087e-2f);
    p = fmaf(p, f, 2.40226507e-1f);
    p = fmaf(p, f, 6.93147181e-1f);
    p = fmaf(p, f, 1.0f);
    return __int_as_float(__float_as_int(p) + (e << 23));
}

#define LDT 40   /* smem tile stride in halves (80B rows) */

// ============================================================
// 2-term fp16 GEMM, register-prefetch double buffered.
// Output projection (plain + bias).
// ============================================================
__global__ void __launch_bounds__(256, 2)
out_gemm(const float* __restrict__ Ag, const float* __restrict__ Bg,
         const float* __restrict__ bias, float* __restrict__ Cg)
{
    constexpr int KDIM = MODEL_DIM;
    constexpr int ABUF = 128 * LDT;
    constexpr int BBUF = 128 * LDT;

    extern __shared__ __half hsm[];
    __half* sAh = hsm;
    __half* sBh = sAh + 2 * ABUF;
    __half* sBl = sBh + 2 * BBUF;

    const int tid = threadIdx.x;
    const int wid = tid >> 5;
    const int lane = tid & 31;
    const int m0 = blockIdx.x * 128;
    const int n0 = blockIdx.y * 128;

    const int warp_m = wid >> 2, warp_n = wid & 3;
    const int wm0 = warp_m * 64, wn0 = warp_n * 32;

    const float* A = Ag;
    const float* B = Bg;

    float acc[4][4][4];
#pragma unroll
    for (int i = 0; i < 4; i++)
#pragma unroll
        for (int j = 0; j < 4; j++)
#pragma unroll
            for (int e = 0; e < 4; e++) acc[i][j][e] = 0.f;

    float4 av[4], bv[4];

    auto ldgA = [&](int c) {
#pragma unroll
        for (int g = 0; g < 4; g++) {
            int id = tid + g * 256;
            int row = id >> 3, q = id & 7;
            av[g] = *(const float4*)(A + (long)(m0 + row) * KDIM + c * 32 + q * 4);
        }
    };
    auto ldgB = [&](int c) {
#pragma unroll
        for (int g = 0; g < 4; g++) {
            int id = tid + g * 256;
            int row = id >> 3, q = id & 7;
            bv[g] = *(const float4*)(B + (long)(n0 + row) * KDIM + c * 32 + q * 4);
        }
    };
    auto sts = [&](int bu) {
        __half* dAh = sAh + bu * ABUF;
        __half* dBh = sBh + bu * BBUF;
        __half* dBl = sBl + bu * BBUF;
#pragma unroll
        for (int g = 0; g < 4; g++) {
            int id = tid + g * 256;
            int row = id >> 3, q = id & 7;
            __half h0 = __float2half_rn(av[g].x), h1 = __float2half_rn(av[g].y);
            __half h2 = __float2half_rn(av[g].z), h3 = __float2half_rn(av[g].w);
            *(uint2*)&dAh[row * LDT + q * 4] = make_uint2(pack_h2(h0, h1), pack_h2(h2, h3));
            __half l0, l1, l2, l3;
            cvt_split(bv[g].x, h0, l0); cvt_split(bv[g].y, h1, l1);
            cvt_split(bv[g].z, h2, l2); cvt_split(bv[g].w, h3, l3);
            *(uint2*)&dBh[row * LDT + q * 4] = make_uint2(pack_h2(h0, h1), pack_h2(h2, h3));
            *(uint2*)&dBl[row * LDT + q * 4] = make_uint2(pack_h2(l0, l1), pack_h2(l2, l3));
        }
    };

    const int nchunks = KDIM >> 5;
    ldgA(0); ldgB(0); sts(0);

    for (int c = 0; c < nchunks; c++) {
        if (c + 1 < nchunks) { ldgA(c + 1); ldgB(c + 1); }
        __syncthreads();

        const int bu = c & 1;
        const u32 aH = smem_u32(sAh + bu * ABUF);
        const u32 bH = smem_u32(sBh + bu * BBUF);
        const u32 bL = smem_u32(sBl + bu * BBUF);
#pragma unroll
        for (int ks = 0; ks < 2; ks++) {
            const int k0 = ks * 16;
            u32 ah[4][4], bh[4][2], bl[4][2];
#pragma unroll
            for (int mt = 0; mt < 4; mt++) {
                u32 off = (u32)(((wm0 + mt * 16 + (lane & 15)) * LDT
                                 + k0 + (lane >> 4) * 8) * 2);
                ldsm4(ah[mt][0], ah[mt][1], ah[mt][2], ah[mt][3], aH + off);
            }
#pragma unroll
            for (int np = 0; np < 2; np++) {
                u32 off = (u32)(((wn0 + np * 16 + (lane & 7) + ((lane >> 4) << 3)) * LDT
                                 + k0 + ((lane >> 3) & 1) * 8) * 2);
                u32 r0, r1, r2, r3;
                ldsm4(r0, r1, r2, r3, bH + off);
                bh[2 * np][0] = r0; bh[2 * np][1] = r1;
                bh[2 * np + 1][0] = r2; bh[2 * np + 1][1] = r3;
                ldsm4(r0, r1, r2, r3, bL + off);
                bl[2 * np][0] = r0; bl[2 * np][1] = r1;
                bl[2 * np + 1][0] = r2; bl[2 * np + 1][1] = r3;
            }
#pragma unroll
            for (int mt = 0; mt < 4; mt++)
#pragma unroll
                for (int nt = 0; nt < 4; nt++)
                    mma_f16(acc[mt][nt], ah[mt][0], ah[mt][1], ah[mt][2], ah[mt][3],
                            bh[nt][0], bh[nt][1]);
#pragma unroll
            for (int mt = 0; mt < 4; mt++)
#pragma unroll
                for (int nt = 0; nt < 4; nt++)
                    mma_f16(acc[mt][nt], ah[mt][0], ah[mt][1], ah[mt][2], ah[mt][3],
                            bl[nt][0], bl[nt][1]);
        }
        if (c + 1 < nchunks) sts((c + 1) & 1);
    }

    const int r_lo = lane >> 2;
    const int cp = (lane & 3) * 2;
#pragma unroll
    for (int mt = 0; mt < 4; mt++) {
#pragma unroll
        for (int nt = 0; nt < 4; nt++) {
            const int n = n0 + wn0 + nt * 8 + cp;
#pragma unroll
            for (int half = 0; half < 2; half++) {
                const int m = m0 + wm0 + mt * 16 + r_lo + half * 8;
                float c0 = acc[mt][nt][half * 2] + bias[n];
                float c1 = acc[mt][nt][half * 2 + 1] + bias[n + 1];
                *(float2*)(Cg + (long)m * MODEL_DIM + n) = make_float2(c0, c1);
            }
        }
    }
}

// ============================================================
// Merged QKV projection (3-term fp16, round-8 verified).
// ============================================================
__global__ void __launch_bounds__(256)
qkv_gemm(const float* __restrict__ A0, const float* __restrict__ A1, const float* __restrict__ A2,
         const float* __restrict__ W0, const float* __restrict__ W1, const float* __restrict__ W2,
         const float* __restrict__ b0, const float* __restrict__ b1, const float* __restrict__ b2,
         float* __restrict__ C0, float* __restrict__ C1, float* __restrict__ C2)
{
    __shared__ __align__(16) __half sAh[128 * LDT];
    __shared__ __align__(16) __half sAl[128 * LDT];
    __shared__ __align__(16) __half sBh[128 * LDT];
    __shared__ __align__(16) __half sBl[128 * LDT];

    const int tid = threadIdx.x;
    const int wid = tid >> 5;
    const int lane = tid & 31;
    const int m0 = blockIdx.x * 128;
    const int n0 = blockIdx.y * 128;
    const int z = blockIdx.z;

    const float* A    = (z == 0) ? A0 : (z == 1) ? A1 : A2;
    const float* W    = (z == 0) ? W0 : (z == 1) ? W1 : W2;
    const float* bias = (z == 0) ? b0 : (z == 1) ? b1 : b2;
    float* Cg         = (z == 0) ? C0 : (z == 1) ? C1 : C2;

    const int warp_m = wid >> 2, warp_n = wid & 3;
    const int wm0 = warp_m * 64, wn0 = warp_n * 32;

    const u32 aH = smem_u32(sAh), aL = smem_u32(sAl);
    const u32 bH = smem_u32(sBh), bL = smem_u32(sBl);

    float acc[4][4][4];
#pragma unroll
    for (int i = 0; i < 4; i++)
#pragma unroll
        for (int j = 0; j < 4; j++)
#pragma unroll
            for (int e = 0; e < 4; e++) acc[i][j][e] = 0.f;

    for (int c = 0; c < (MODEL_DIM >> 5); c++) {
#pragma unroll
        for (int g = 0; g < 4; g++) {
            int id = tid + g * 256;
            int row = id >> 3, q = id & 7;
            float4 v = *(const float4*)(A + (long)(m0 + row) * MODEL_DIM + c * 32 + q * 4);
            __half h0, h1, h2, h3, l0, l1, l2, l3;
            cvt_split(v.x, h0, l0); cvt_split(v.y, h1, l1);
            cvt_split(v.z, h2, l2); cvt_split(v.w, h3, l3);
            *(uint2*)&sAh[row * LDT + q * 4] = make_uint2(pack_h2(h0, h1), pack_h2(h2, h3));
            *(uint2*)&sAl[row * LDT + q * 4] = make_uint2(pack_h2(l0, l1), pack_h2(l2, l3));
            float4 w = *(const float4*)(W + (long)(n0 + row) * MODEL_DIM + c * 32 + q * 4);
            cvt_split(w.x, h0, l0); cvt_split(w.y, h1, l1);
            cvt_split(w.z, h2, l2); cvt_split(w.w, h3, l3);
            *(uint2*)&sBh[row * LDT + q * 4] = make_uint2(pack_h2(h0, h1), pack_h2(h2, h3));
            *(uint2*)&sBl[row * LDT + q * 4] = make_uint2(pack_h2(l0, l1), pack_h2(l2, l3));
        }
        __syncthreads();

#pragma unroll
        for (int ks = 0; ks < 2; ks++) {
            const int k0 = ks * 16;
            u32 ah[4][4], al[4][4], bh[4][2], bl[4][2];
#pragma unroll
            for (int mt = 0; mt < 4; mt++) {
                u32 off = (u32)(((wm0 + mt * 16 + (lane & 15)) * LDT
                                 + k0 + (lane >> 4) * 8) * 2);
                ldsm4(ah[mt][0], ah[mt][1], ah[mt][2], ah[mt][3], aH + off);
                ldsm4(al[mt][0], al[mt][1], al[mt][2], al[mt][3], aL + off);
            }
#pragma unroll
            for (int np = 0; np < 2; np++) {
                u32 off = (u32)(((wn0 + np * 16 + (lane & 7) + ((lane >> 4) << 3)) * LDT
                                 + k0 + ((lane >> 3) & 1) * 8) * 2);
                u32 r0, r1, r2, r3;
                ldsm4(r0, r1, r2, r3, bH + off);
                bh[2 * np][0] = r0; bh[2 * np][1] = r1;
                bh[2 * np + 1][0] = r2; bh[2 * np + 1][1] = r3;
                ldsm4(r0, r1, r2, r3, bL + off);
                bl[2 * np][0] = r0; bl[2 * np][1] = r1;
                bl[2 * np + 1][0] = r2; bl[2 * np + 1][1] = r3;
            }
#pragma unroll
            for (int mt = 0; mt < 4; mt++)
#pragma unroll
                for (int nt = 0; nt < 4; nt++)
                    mma_f16(acc[mt][nt], ah[mt][0], ah[mt][1], ah[mt][2], ah[mt][3],
                            bh[nt][0], bh[nt][1]);
#pragma unroll
            for (int mt = 0; mt < 4; mt++)
#pragma unroll
                for (int nt = 0; nt < 4; nt++)
                    mma_f16(acc[mt][nt], ah[mt][0], ah[mt][1], ah[mt][2], ah[mt][3],
                            bl[nt][0], bl[nt][1]);
#pragma unroll
            for (int mt = 0; mt < 4; mt++)
#pragma unroll
                for (int nt = 0; nt < 4; nt++)
                    mma_f16(acc[mt][nt], al[mt][0], al[mt][1], al[mt][2], al[mt][3],
                            bh[nt][0], bh[nt][1]);
        }
        __syncthreads();
    }

    const int r_lo = lane >> 2;
    const int cp = (lane & 3) * 2;
#pragma unroll
    for (int mt = 0; mt < 4; mt++) {
#pragma unroll
        for (int nt = 0; nt < 4; nt++) {
            const int n = n0 + wn0 + nt * 8 + cp;
#pragma unroll
            for (int half = 0; half < 2; half++) {
                const int m = m0 + wm0 + mt * 16 + r_lo + half * 8;
                float c0 = acc[mt][nt][half * 2] + bias[n];
                float c1 = acc[mt][nt][half * 2 + 1] + bias[n + 1];
                int b = m >> 11, s = m & (SEQ - 1);
                int h = n >> 6, d = n & 63;
                float* dst = Cg + (((long)(b * N_HEAD + h) * SEQ) + s) * HEAD_DIM + d;
                *(float2*)dst = make_float2(c0, c1);
            }
        }
    }
}

// ============================================================
// FULLY fused attention: scores + softmax + PV, one kernel.
// (round-9 design + quad-reduction fix for row sums)
// ============================================================
#define FLDT 72                 /* Q/K smem stride (halves) */
#define VN 72                   /* V [k][n] smem stride (halves) */
#define STG_OFF 0               /* 2 x 16384 floats (K 8192 + V 8192) */
#define QH_OFF  131072
#define KH_OFF  (QH_OFF + 128 * FLDT * 2)
#define KL_OFF  (KH_OFF + 128 * FLDT * 2)
#define VH_OFF  (KL_OFF + 128 * FLDT * 2)
#define VL_OFF  (VH_OFF + 128 * VN * 2)
#define LINV_OFF (VL_OFF + 128 * VN * 2)
#define FA_SMEM (LINV_OFF + 128 * 4)     /* 223744 B */

__global__ void __launch_bounds__(256)
fused_attn(const float* __restrict__ Qg, const float* __restrict__ Kg,
           const float* __restrict__ Vg, float* __restrict__ P,
           float* __restrict__ ctx)
{
    extern __shared__ char dsm[];
    float* stg   = (float*)(dsm + STG_OFF);
    __half* sQh  = (__half*)(dsm + QH_OFF);
    __half* sKh  = (__half*)(dsm + KH_OFF);
    __half* sKl  = (__half*)(dsm + KL_OFF);
    __half* sVh  = (__half*)(dsm + VH_OFF);
    __half* sVl  = (__half*)(dsm + VL_OFF);
    float* linv  = (float*)(dsm + LINV_OFF);

    const int tid = threadIdx.x;
    const int wid = tid >> 5;
    const int lane = tid & 31;
    const int m0 = blockIdx.x * 128;
    const int bh = blockIdx.y;
    const int bb = bh / N_HEAD, hh = bh % N_HEAD;

    const float* Q = Qg + ((long)bh * SEQ + m0) * HEAD_DIM;
    const float* K = Kg + (long)bh * SEQ * HEAD_DIM;
    const float* V = Vg + (long)bh * SEQ * HEAD_DIM;
    float* Pb = P + ((long)bh * SEQ + m0) * SEQ;

    // ---- Q tile 128x64 (hi halves only) ----
#pragma unroll
    for (int g = 0; g < 8; g++) {
        int fid = tid + g * 256;
        int row = fid >> 4, q = fid & 15;
        float4 v = *(const float4*)(Q + row * HEAD_DIM + q * 4);
        __half h0 = __float2half_rn(v.x), h1 = __float2half_rn(v.y);
        __half h2 = __float2half_rn(v.z), h3 = __float2half_rn(v.w);
        *(uint2*)&sQh[row * FLDT + q * 4] = make_uint2(pack_h2(h0, h1), pack_h2(h2, h3));
    }

    const u32 stgB = smem_u32(stg);
    // ---- prefetch chunk 0 (K + V) ----
    {
        const float* Ks = K;
        const float* Vs = V;
#pragma unroll
        for (int g = 0; g < 16; g++) {
            int fid = tid + g * 256;
            const float* s = (g < 8) ? (Ks + fid * 4) : (Vs + (fid - 2048) * 4);
            CP_ASYNC16(stgB + fid * 16, s);
        }
        CP_COMMIT();
    }

    const u32 aH = smem_u32(sQh);
    const u32 bH = smem_u32(sKh), bL = smem_u32(sKl);
    const u32 vH = smem_u32(sVh), vL = smem_u32(sVl);
    const int r_lo = lane >> 2;
    const int cp2 = (lane & 3) * 2;
    const int row_r = wid * 16 + r_lo;

    float rs0 = 0.f, rs1 = 0.f;
    float o[8][4];
#pragma unroll
    for (int i = 0; i < 8; i++)
#pragma unroll
        for (int e = 0; e < 4; e++) o[i][e] = 0.f;

    for (int c = 0; c < 16; c++) {
        if (c < 15) {
            const float* Ks = K + (long)(c + 1) * 8192;
            const float* Vs = V + (long)(c + 1) * 8192;
            u32 dst = stgB + ((c + 1) & 1) * 65536;
#pragma unroll
            for (int g = 0; g < 16; g++) {
                int fid = tid + g * 256;
                const float* s = (g < 8) ? (Ks + fid * 4) : (Vs + (fid - 2048) * 4);
                CP_ASYNC16(dst + fid * 16, s);
            }
            CP_COMMIT();
            CP_WAIT1();
        } else {
            CP_WAIT0();
        }
        __syncthreads();

        // ---- convert staged K -> hi/lo [n][k], V -> hi/lo [k][n] ----
        {
            const float* sb = stg + (c & 1) * 16384;
#pragma unroll
            for (int g = 0; g < 8; g++) {
                int fid = tid + g * 256;
                int row = fid >> 4, q = fid & 15;
                float4 v = *(const float4*)(sb + row * 64 + q * 4);
                __half h0, h1, h2, h3, l0, l1, l2, l3;
                cvt_split(v.x, h0, l0); cvt_split(v.y, h1, l1);
                cvt_split(v.z, h2, l2); cvt_split(v.w, h3, l3);
                *(uint2*)&sKh[row * FLDT + q * 4] = make_uint2(pack_h2(h0, h1), pack_h2(h2, h3));
                *(uint2*)&sKl[row * FLDT + q * 4] = make_uint2(pack_h2(l0, l1), pack_h2(l2, l3));
            }
#pragma unroll
            for (int g = 0; g < 8; g++) {
                int fid = tid + g * 256;
                int k = fid >> 4, nq = fid & 15;
                float4 v = *(const float4*)(sb + 8192 + k * 64 + nq * 4);
                __half h0, h1, h2, h3, l0, l1, l2, l3;
                cvt_split(v.x, h0, l0); cvt_split(v.y, h1, l1);
                cvt_split(v.z, h2, l2); cvt_split(v.w, h3, l3);
                *(uint2*)&sVh[k * VN + nq * 4] = make_uint2(pack_h2(h0, h1), pack_h2(h2, h3));
                *(uint2*)&sVl[k * VN + nq * 4] = make_uint2(pack_h2(l0, l1), pack_h2(l2, l3));
            }
        }
        __syncthreads();

        // ---- QK^T + exp + P store + pack A frags (two 64-key halves) ----
        u32 pa[8][4];
#pragma unroll
        for (int half = 0; half < 2; half++) {
            float sc[8][4];
#pragma unroll
            for (int i = 0; i < 8; i++)
#pragma unroll
                for (int e = 0; e < 4; e++) sc[i][e] = 0.f;

#pragma unroll
            for (int ks = 0; ks < 4; ks++) {
                const int k0 = ks * 16;
                u32 a0, a1, a2, a3;
                {
                    u32 off = (u32)(((wid * 16 + (lane & 15)) * FLDT
                                     + k0 + (lane >> 4) * 8) * 2);
                    ldsm4(a0, a1, a2, a3, aH + off);
                }
#pragma unroll
                for (int np = 0; np < 4; np++) {
                    const int n0 = half * 64 + np * 16;
                    u32 off = (u32)(((n0 + (lane & 7) + ((lane >> 4) << 3)) * FLDT
                                     + k0 + ((lane >> 3) & 1) * 8) * 2);
                    u32 r0, r1, r2, r3;
                    ldsm4(r0, r1, r2, r3, bH + off);
                    mma_f16(sc[np * 2],     a0, a1, a2, a3, r0, r1);
                    mma_f16(sc[np * 2 + 1], a0, a1, a2, a3, r2, r3);
                    ldsm4(r0, r1, r2, r3, bL + off);
                    mma_f16(sc[np * 2],     a0, a1, a2, a3, r0, r1);
                    mma_f16(sc[np * 2 + 1], a0, a1, a2, a3, r2, r3);
                }
            }
#pragma unroll
            for (int ntl = 0; ntl < 8; ntl++) {
                float e0 = fast_exp(sc[ntl][0] * 0.125f);
                float e1 = fast_exp(sc[ntl][1] * 0.125f);
                float e2 = fast_exp(sc[ntl][2] * 0.125f);
                float e3 = fast_exp(sc[ntl][3] * 0.125f);
                rs0 += e0 + e1;
                rs1 += e2 + e3;
                const int n = c * 128 + half * 64 + ntl * 8 + cp2;
                *(float2*)(Pb + (long)row_r * SEQ + n)       = make_float2(e0, e1);
                *(float2*)(Pb + (long)(row_r + 8) * SEQ + n) = make_float2(e2, e3);
                const int kt = half * 4 + (ntl >> 1);
                pa[kt][(ntl & 1) * 2]     = pack_h2(__float2half_rn(e0), __float2half_rn(e1));
                pa[kt][(ntl & 1) * 2 + 1] = pack_h2(__float2half_rn(e2), __float2half_rn(e3));
            }
        }

        // ---- PV: O += E @ V  (V hi + lo) ----
#pragma unroll
        for (int kt = 0; kt < 8; kt++) {
            const int k0 = kt * 16;
            u32 vh[8][2], vl[8][2];
#pragma unroll
            for (int np2 = 0; np2 < 4; np2++) {
                const int n0 = np2 * 16;
                u32 off = (u32)(((k0 + (lane & 15)) * VN + n0 + (lane >> 4) * 8) * 2);
                u32 r0, r1, r2, r3;
                ldsm4t(r0, r1, r2, r3, vH + off);
                vh[np2 * 2][0] = r0; vh[np2 * 2][1] = r1;
                vh[np2 * 2 + 1][0] = r2; vh[np2 * 2 + 1][1] = r3;
                ldsm4t(r0, r1, r2, r3, vL + off);
                vl[np2 * 2][0] = r0; vl[np2 * 2][1] = r1;
                vl[np2 * 2 + 1][0] = r2; vl[np2 * 2 + 1][1] = r3;
            }
#pragma unroll
            for (int nt2 = 0; nt2 < 8; nt2++)
                mma_f16(o[nt2], pa[kt][0], pa[kt][1], pa[kt][2], pa[kt][3],
                        vh[nt2][0], vh[nt2][1]);
#pragma unroll
            for (int nt2 = 0; nt2 < 8; nt2++)
                mma_f16(o[nt2], pa[kt][0], pa[kt][1], pa[kt][2], pa[kt][3],
                        vl[nt2][0], vl[nt2][1]);
        }
    }

    // ---- FIX: reduce row sums across the quad (lanes sharing a row) ----
    rs0 += __shfl_xor_sync(0xffffffffu, rs0, 1);
    rs0 += __shfl_xor_sync(0xffffffffu, rs0, 2);
    rs1 += __shfl_xor_sync(0xffffffffu, rs1, 1);
    rs1 += __shfl_xor_sync(0xffffffffu, rs1, 2);

    // ---- normalize O, write ctx ----
    const float i0 = 1.f / rs0;
    const float i1 = 1.f / rs1;
    {
        const long base0 = ((long)(bb * SEQ + m0 + row_r)) * MODEL_DIM + hh * HEAD_DIM;
        const long base1 = base0 + 8L * MODEL_DIM;
#pragma unroll
        for (int nt2 = 0; nt2 < 8; nt2++) {
            const int col = nt2 * 8 + cp2;
            *(float2*)(ctx + base0 + col) = make_float2(o[nt2][0] * i0, o[nt2][1] * i0);
            *(float2*)(ctx + base1 + col) = make_float2(o[nt2][2] * i1, o[nt2][3] * i1);
        }
    }
    if ((lane & 3) == 0) {
        linv[row_r] = i0;
        linv[row_r + 8] = i1;
    }
    __syncthreads();

    // ---- fixup: normalize block's 128x2048 P region (L2-hot) ----
    float4* p4 = (float4*)Pb;
#pragma unroll 4
    for (int idx = tid; idx < 128 * 512; idx += 256) {
        float inv = linv[idx >> 9];
        float4 v = p4[idx];
        v.x *= inv; v.y *= inv; v.z *= inv; v.w *= inv;
        p4[idx] = v;
    }
}

// ============================================================
// Host launch
// ============================================================
extern "C" void kernel_launch(void* const* d_in, const int* in_sizes, int n_in,
                              void* d_out, int out_size)
{
    const float* q    = (const float*)d_in[0];
    const float* k    = (const float*)d_in[1];
    const float* v    = (const float*)d_in[2];
    const float* wq_w = (const float*)d_in[3];
    const float* wq_b = (const float*)d_in[4];
    const float* wk_w = (const float*)d_in[5];
    const float* wk_b = (const float*)d_in[6];
    const float* wv_w = (const float*)d_in[7];
    const float* wv_b = (const float*)d_in[8];
    const float* wo_w = (const float*)d_in[9];
    const float* wo_b = (const float*)d_in[10];
    float* out = (float*)d_out;

    float *qh, *kh, *vh, *ctx;
    cudaGetSymbolAddress((void**)&qh, g_qh);
    cudaGetSymbolAddress((void**)&kh, g_kh);
    cudaGetSymbolAddress((void**)&vh, g_vh);
    cudaGetSymbolAddress((void**)&ctx, g_ctx);

    float* attnW = out + (long)M_TOT * MODEL_DIM;

    const int SMEM_OUT = (2 * 128 * LDT + 4 * 128 * LDT) * 2;   // 61440 B

    cudaFuncSetAttribute(fused_attn,
                         cudaFuncAttributeMaxDynamicSharedMemorySize, FA_SMEM);
    cudaFuncSetAttribute(out_gemm,
                         cudaFuncAttributeMaxDynamicSharedMemorySize, SMEM_OUT);

    dim3 gqkv(M_TOT / 128, MODEL_DIM / 128, 3);           // (32, 6, 3)
    qkv_gemm<<<gqkv, 256>>>(q, k, v, wq_w, wk_w, wv_w,
                            wq_b, wk_b, wv_b, qh, kh, vh);

    dim3 gfa(SEQ / 128, BHEADS);                          // (16, 24)
    fused_attn<<<gfa, 256, FA_SMEM>>>(qh, kh, vh, attnW, ctx);

    dim3 gout(M_TOT / 128, MODEL_DIM / 128, 1);           // (32, 6)
    out_gemm<<<gout, 256, SMEM_OUT>>>(ctx, wo_w, wo_b, out);
}

// round 16
// speedup vs baseline: 11.8567x; 1.0327x over previous
#include <cuda_runtime.h>
#include <cuda_fp16.h>

#define MODEL_DIM 768
#define N_HEAD 12
#define HEAD_DIM 64
#define SEQ 2048
#define M_TOT 4096
#define BHEADS 24

typedef unsigned int u32;

// -------- device scratch (no allocations allowed) --------
// Q/K/V stored pre-split as fp16 (hi/lo); ctx as fp16 hi.
__device__ __half g_qhi[BHEADS * SEQ * HEAD_DIM];
__device__ __half g_khi[BHEADS * SEQ * HEAD_DIM];
__device__ __half g_klo[BHEADS * SEQ * HEAD_DIM];
__device__ __half g_vhi[BHEADS * SEQ * HEAD_DIM];
__device__ __half g_vlo[BHEADS * SEQ * HEAD_DIM];
__device__ __half g_ctxh[M_TOT * MODEL_DIM];

// ============================================================
// helpers
// ============================================================
__device__ __forceinline__ u32 smem_u32(const void* p) {
    u32 a;
    asm("{ .reg .u64 t; cvta.to.shared.u64 t, %1; cvt.u32.u64 %0, t; }"
        : "=r"(a) : "l"(p));
    return a;
}

__device__ __forceinline__ void ldsm4(u32& r0, u32& r1, u32& r2, u32& r3, u32 addr) {
    asm volatile("ldmatrix.sync.aligned.m8n8.x4.shared.b16 {%0,%1,%2,%3}, [%4];"
        : "=r"(r0), "=r"(r1), "=r"(r2), "=r"(r3) : "r"(addr));
}

__device__ __forceinline__ void ldsm4t(u32& r0, u32& r1, u32& r2, u32& r3, u32 addr) {
    asm volatile("ldmatrix.sync.aligned.m8n8.x4.trans.shared.b16 {%0,%1,%2,%3}, [%4];"
        : "=r"(r0), "=r"(r1), "=r"(r2), "=r"(r3) : "r"(addr));
}

__device__ __forceinline__ void mma_f16(float* c, u32 a0, u32 a1, u32 a2, u32 a3,
                                        u32 b0, u32 b1) {
    asm volatile(
        "mma.sync.aligned.m16n8k16.row.col.f32.f16.f16.f32 "
        "{%0,%1,%2,%3}, {%4,%5,%6,%7}, {%8,%9}, {%0,%1,%2,%3};"
        : "+f"(c[0]), "+f"(c[1]), "+f"(c[2]), "+f"(c[3])
        : "r"(a0), "r"(a1), "r"(a2), "r"(a3), "r"(b0), "r"(b1));
}

#define CP_ASYNC16(d, s) asm volatile("cp.async.cg.shared.global [%0], [%1], 16;" :: "r"(d), "l"(s) : "memory")
#define CP_COMMIT()      asm volatile("cp.async.commit_group;" ::: "memory")
#define CP_WAIT1()       asm volatile("cp.async.wait_group 1;" ::: "memory")
#define CP_WAIT0()       asm volatile("cp.async.wait_group 0;" ::: "memory")

__device__ __forceinline__ u32 pack_h2(__half a, __half b) {
    __half2 p(a, b);
    return *reinterpret_cast<u32*>(&p);
}

__device__ __forceinline__ void cvt_split(float x, __half& h, __half& l) {
    h = __float2half_rn(x);
    l = __float2half_rn(x - __half2float(h));
}

__device__ __forceinline__ float fast_exp(float x)
{
    const float L2E = 1.4426950408889634f;
    float t = fmaf(x, L2E, 12582912.0f);
    int e = __float_as_int(t) - 0x4B400000;
    float fi = t - 12582912.0f;
    float f = fmaf(x, L2E, -fi);
    float p = 1.53953850e-4f;
    p = fmaf(p, f, 1.33335581e-3f);
    p = fmaf(p, f, 9.61812911e-3f);
    p = fmaf(p, f, 5.55041087e-2f);
    p = fmaf(p, f, 2.40226507e-1f);
    p = fmaf(p, f, 6.93147181e-1f);
    p = fmaf(p, f, 1.0f);
    return __int_as_float(__float_as_int(p) + (e << 23));
}

#define LDT 40   /* smem tile stride in halves (80B rows) */

// ============================================================
// Output projection: A = ctx (fp16 hi, no conversion needed),
// B = weights fp32 split hi/lo. Register-prefetch pipelined.
// ============================================================
__global__ void __launch_bounds__(256, 2)
out_gemm(const __half* __restrict__ Ag, const float* __restrict__ Bg,
         const float* __restrict__ bias, float* __restrict__ Cg)
{
    constexpr int KDIM = MODEL_DIM;
    constexpr int ABUF = 128 * LDT;
    constexpr int BBUF = 128 * LDT;

    extern __shared__ __half hsm[];
    __half* sAh = hsm;
    __half* sBh = sAh + 2 * ABUF;
    __half* sBl = sBh + 2 * BBUF;

    const int tid = threadIdx.x;
    const int wid = tid >> 5;
    const int lane = tid & 31;
    const int m0 = blockIdx.x * 128;
    const int n0 = blockIdx.y * 128;

    const int warp_m = wid >> 2, warp_n = wid & 3;
    const int wm0 = warp_m * 64, wn0 = warp_n * 32;

    float acc[4][4][4];
#pragma unroll
    for (int i = 0; i < 4; i++)
#pragma unroll
        for (int j = 0; j < 4; j++)
#pragma unroll
            for (int e = 0; e < 4; e++) acc[i][j][e] = 0.f;

    uint4 avh[2];
    float4 bv[4];

    auto ldgA = [&](int c) {
#pragma unroll
        for (int g = 0; g < 2; g++) {
            int id = tid + g * 256;
            int row = id >> 2, q = id & 3;
            avh[g] = *(const uint4*)(Ag + (long)(m0 + row) * KDIM + c * 32 + q * 8);
        }
    };
    auto ldgB = [&](int c) {
#pragma unroll
        for (int g = 0; g < 4; g++) {
            int id = tid + g * 256;
            int row = id >> 3, q = id & 7;
            bv[g] = *(const float4*)(Bg + (long)(n0 + row) * KDIM + c * 32 + q * 4);
        }
    };
    auto sts = [&](int bu) {
        __half* dAh = sAh + bu * ABUF;
        __half* dBh = sBh + bu * BBUF;
        __half* dBl = sBl + bu * BBUF;
#pragma unroll
        for (int g = 0; g < 2; g++) {
            int id = tid + g * 256;
            int row = id >> 2, q = id & 3;
            *(uint4*)&dAh[row * LDT + q * 8] = avh[g];
        }
#pragma unroll
        for (int g = 0; g < 4; g++) {
            int id = tid + g * 256;
            int row = id >> 3, q = id & 7;
            __half h0, h1, h2, h3, l0, l1, l2, l3;
            cvt_split(bv[g].x, h0, l0); cvt_split(bv[g].y, h1, l1);
            cvt_split(bv[g].z, h2, l2); cvt_split(bv[g].w, h3, l3);
            *(uint2*)&dBh[row * LDT + q * 4] = make_uint2(pack_h2(h0, h1), pack_h2(h2, h3));
            *(uint2*)&dBl[row * LDT + q * 4] = make_uint2(pack_h2(l0, l1), pack_h2(l2, l3));
        }
    };

    const int nchunks = KDIM >> 5;
    ldgA(0); ldgB(0); sts(0);

    for (int c = 0; c < nchunks; c++) {
        if (c + 1 < nchunks) { ldgA(c + 1); ldgB(c + 1); }
        __syncthreads();

        const int bu = c & 1;
        const u32 aH = smem_u32(sAh + bu * ABUF);
        const u32 bH = smem_u32(sBh + bu * BBUF);
        const u32 bL = smem_u32(sBl + bu * BBUF);
#pragma unroll
        for (int ks = 0; ks < 2; ks++) {
            const int k0 = ks * 16;
            u32 ah[4][4], bh[4][2], bl[4][2];
#pragma unroll
            for (int mt = 0; mt < 4; mt++) {
                u32 off = (u32)(((wm0 + mt * 16 + (lane & 15)) * LDT
                                 + k0 + (lane >> 4) * 8) * 2);
                ldsm4(ah[mt][0], ah[mt][1], ah[mt][2], ah[mt][3], aH + off);
            }
#pragma unroll
            for (int np = 0; np < 2; np++) {
                u32 off = (u32)(((wn0 + np * 16 + (lane & 7) + ((lane >> 4) << 3)) * LDT
                                 + k0 + ((lane >> 3) & 1) * 8) * 2);
                u32 r0, r1, r2, r3;
                ldsm4(r0, r1, r2, r3, bH + off);
                bh[2 * np][0] = r0; bh[2 * np][1] = r1;
                bh[2 * np + 1][0] = r2; bh[2 * np + 1][1] = r3;
                ldsm4(r0, r1, r2, r3, bL + off);
                bl[2 * np][0] = r0; bl[2 * np][1] = r1;
                bl[2 * np + 1][0] = r2; bl[2 * np + 1][1] = r3;
            }
#pragma unroll
            for (int mt = 0; mt < 4; mt++)
#pragma unroll
                for (int nt = 0; nt < 4; nt++)
                    mma_f16(acc[mt][nt], ah[mt][0], ah[mt][1], ah[mt][2], ah[mt][3],
                            bh[nt][0], bh[nt][1]);
#pragma unroll
            for (int mt = 0; mt < 4; mt++)
#pragma unroll
                for (int nt = 0; nt < 4; nt++)
                    mma_f16(acc[mt][nt], ah[mt][0], ah[mt][1], ah[mt][2], ah[mt][3],
                            bl[nt][0], bl[nt][1]);
        }
        if (c + 1 < nchunks) sts((c + 1) & 1);
    }

    const int r_lo = lane >> 2;
    const int cp = (lane & 3) * 2;
#pragma unroll
    for (int mt = 0; mt < 4; mt++) {
#pragma unroll
        for (int nt = 0; nt < 4; nt++) {
            const int n = n0 + wn0 + nt * 8 + cp;
#pragma unroll
            for (int half = 0; half < 2; half++) {
                const int m = m0 + wm0 + mt * 16 + r_lo + half * 8;
                float c0 = acc[mt][nt][half * 2] + bias[n];
                float c1 = acc[mt][nt][half * 2 + 1] + bias[n + 1];
                *(float2*)(Cg + (long)m * MODEL_DIM + n) = make_float2(c0, c1);
            }
        }
    }
}

// ============================================================
// Merged QKV projection (3-term fp16, round-8 verified core).
// Epilogue writes fp16: Q hi only; K/V hi+lo (pre-split).
// ============================================================
__global__ void __launch_bounds__(256)
qkv_gemm(const float* __restrict__ A0, const float* __restrict__ A1, const float* __restrict__ A2,
         const float* __restrict__ W0, const float* __restrict__ W1, const float* __restrict__ W2,
         const float* __restrict__ b0, const float* __restrict__ b1, const float* __restrict__ b2,
         __half* __restrict__ Qhi, __half* __restrict__ Khi, __half* __restrict__ Klo,
         __half* __restrict__ Vhi, __half* __restrict__ Vlo)
{
    __shared__ __align__(16) __half sAh[128 * LDT];
    __shared__ __align__(16) __half sAl[128 * LDT];
    __shared__ __align__(16) __half sBh[128 * LDT];
    __shared__ __align__(16) __half sBl[128 * LDT];

    const int tid = threadIdx.x;
    const int wid = tid >> 5;
    const int lane = tid & 31;
    const int m0 = blockIdx.x * 128;
    const int n0 = blockIdx.y * 128;
    const int z = blockIdx.z;

    const float* A    = (z == 0) ? A0 : (z == 1) ? A1 : A2;
    const float* W    = (z == 0) ? W0 : (z == 1) ? W1 : W2;
    const float* bias = (z == 0) ? b0 : (z == 1) ? b1 : b2;

    const int warp_m = wid >> 2, warp_n = wid & 3;
    const int wm0 = warp_m * 64, wn0 = warp_n * 32;

    const u32 aH = smem_u32(sAh), aL = smem_u32(sAl);
    const u32 bH = smem_u32(sBh), bL = smem_u32(sBl);

    float acc[4][4][4];
#pragma unroll
    for (int i = 0; i < 4; i++)
#pragma unroll
        for (int j = 0; j < 4; j++)
#pragma unroll
            for (int e = 0; e < 4; e++) acc[i][j][e] = 0.f;

    for (int c = 0; c < (MODEL_DIM >> 5); c++) {
#pragma unroll
        for (int g = 0; g < 4; g++) {
            int id = tid + g * 256;
            int row = id >> 3, q = id & 7;
            float4 v = *(const float4*)(A + (long)(m0 + row) * MODEL_DIM + c * 32 + q * 4);
            __half h0, h1, h2, h3, l0, l1, l2, l3;
            cvt_split(v.x, h0, l0); cvt_split(v.y, h1, l1);
            cvt_split(v.z, h2, l2); cvt_split(v.w, h3, l3);
            *(uint2*)&sAh[row * LDT + q * 4] = make_uint2(pack_h2(h0, h1), pack_h2(h2, h3));
            *(uint2*)&sAl[row * LDT + q * 4] = make_uint2(pack_h2(l0, l1), pack_h2(l2, l3));
            float4 w = *(const float4*)(W + (long)(n0 + row) * MODEL_DIM + c * 32 + q * 4);
            cvt_split(w.x, h0, l0); cvt_split(w.y, h1, l1);
            cvt_split(w.z, h2, l2); cvt_split(w.w, h3, l3);
            *(uint2*)&sBh[row * LDT + q * 4] = make_uint2(pack_h2(h0, h1), pack_h2(h2, h3));
            *(uint2*)&sBl[row * LDT + q * 4] = make_uint2(pack_h2(l0, l1), pack_h2(l2, l3));
        }
        __syncthreads();

#pragma unroll
        for (int ks = 0; ks < 2; ks++) {
            const int k0 = ks * 16;
            u32 ah[4][4], al[4][4], bh[4][2], bl[4][2];
#pragma unroll
            for (int mt = 0; mt < 4; mt++) {
                u32 off = (u32)(((wm0 + mt * 16 + (lane & 15)) * LDT
                                 + k0 + (lane >> 4) * 8) * 2);
                ldsm4(ah[mt][0], ah[mt][1], ah[mt][2], ah[mt][3], aH + off);
                ldsm4(al[mt][0], al[mt][1], al[mt][2], al[mt][3], aL + off);
            }
#pragma unroll
            for (int np = 0; np < 2; np++) {
                u32 off = (u32)(((wn0 + np * 16 + (lane & 7) + ((lane >> 4) << 3)) * LDT
                                 + k0 + ((lane >> 3) & 1) * 8) * 2);
                u32 r0, r1, r2, r3;
                ldsm4(r0, r1, r2, r3, bH + off);
                bh[2 * np][0] = r0; bh[2 * np][1] = r1;
                bh[2 * np + 1][0] = r2; bh[2 * np + 1][1] = r3;
                ldsm4(r0, r1, r2, r3, bL + off);
                bl[2 * np][0] = r0; bl[2 * np][1] = r1;
                bl[2 * np + 1][0] = r2; bl[2 * np + 1][1] = r3;
            }
#pragma unroll
            for (int mt = 0; mt < 4; mt++)
#pragma unroll
                for (int nt = 0; nt < 4; nt++)
                    mma_f16(acc[mt][nt], ah[mt][0], ah[mt][1], ah[mt][2], ah[mt][3],
                            bh[nt][0], bh[nt][1]);
#pragma unroll
            for (int mt = 0; mt < 4; mt++)
#pragma unroll
                for (int nt = 0; nt < 4; nt++)
                    mma_f16(acc[mt][nt], ah[mt][0], ah[mt][1], ah[mt][2], ah[mt][3],
                            bl[nt][0], bl[nt][1]);
#pragma unroll
            for (int mt = 0; mt < 4; mt++)
#pragma unroll
                for (int nt = 0; nt < 4; nt++)
                    mma_f16(acc[mt][nt], al[mt][0], al[mt][1], al[mt][2], al[mt][3],
                            bh[nt][0], bh[nt][1]);
        }
        __syncthreads();
    }

    const int r_lo = lane >> 2;
    const int cp = (lane & 3) * 2;
#pragma unroll
    for (int mt = 0; mt < 4; mt++) {
#pragma unroll
        for (int nt = 0; nt < 4; nt++) {
            const int n = n0 + wn0 + nt * 8 + cp;
#pragma unroll
            for (int half = 0; half < 2; half++) {
                const int m = m0 + wm0 + mt * 16 + r_lo + half * 8;
                float c0 = acc[mt][nt][half * 2] + bias[n];
                float c1 = acc[mt][nt][half * 2 + 1] + bias[n + 1];
                int b = m >> 11, s = m & (SEQ - 1);
                int h = n >> 6, d = n & 63;
                long base = (((long)(b * N_HEAD + h) * SEQ) + s) * HEAD_DIM + d;
                if (z == 0) {
                    *(u32*)&Qhi[base] = pack_h2(__float2half_rn(c0), __float2half_rn(c1));
                } else {
                    __half h0, l0, h1, l1;
                    cvt_split(c0, h0, l0);
                    cvt_split(c1, h1, l1);
                    __half* Hi = (z == 1) ? Khi : Vhi;
                    __half* Lo = (z == 1) ? Klo : Vlo;
                    *(u32*)&Hi[base] = pack_h2(h0, h1);
                    *(u32*)&Lo[base] = pack_h2(l0, l1);
                }
            }
        }
    }
}

// ============================================================
// FULLY fused attention: scores + softmax + PV.
// K/V arrive PRE-SPLIT fp16 -> cp.async lands directly in the
// padded MMA layout: no staging, no convert phase.
// smem: Q 18K + 2 x (Kh,Kl,Vh,Vl = 72K) + linv = 166400 B
// ============================================================
#define FLDT 72                 /* padded stride in halves (36 words ≡ 4 mod 8: ldsm conflict-free) */
#define TILE_B (128 * FLDT * 2) /* 18432 B per tile */
#define BUF_B  (4 * TILE_B)     /* KH,KL,VH,VL per buffer */
#define Q_OFF  0
#define BUF_OFF 18432
#define LINV_OFF (BUF_OFF + 2 * BUF_B)
#define FA_SMEM (LINV_OFF + 128 * 4)   /* 166400 */

__global__ void __launch_bounds__(256)
fused_attn(const __half* __restrict__ Qhi, const __half* __restrict__ Khi,
           const __half* __restrict__ Klo, const __half* __restrict__ Vhi,
           const __half* __restrict__ Vlo, float* __restrict__ P,
           __half* __restrict__ ctxh)
{
    extern __shared__ char dsm[];
    __half* sQh = (__half*)(dsm + Q_OFF);
    float* linv = (float*)(dsm + LINV_OFF);

    const int tid = threadIdx.x;
    const int wid = tid >> 5;
    const int lane = tid & 31;
    const int m0 = blockIdx.x * 128;
    const int bh = blockIdx.y;
    const int bb = bh / N_HEAD, hh = bh % N_HEAD;

    const long head_base = (long)bh * SEQ * HEAD_DIM;
    float* Pb = P + ((long)bh * SEQ + m0) * SEQ;

    // ---- Q tile 128x64 fp16 hi: direct load ----
#pragma unroll
    for (int g = 0; g < 4; g++) {
        int fid = tid + g * 256;            // 1024 x 16B chunks
        int row = fid >> 3, q = fid & 7;
        uint4 v = *(const uint4*)(Qhi + head_base + ((long)(m0 + row)) * HEAD_DIM + q * 8);
        *(uint4*)&sQh[row * FLDT + q * 8] = v;
    }

    const u32 smB = smem_u32(dsm);
    const __half* srcs[4] = { Khi + head_base, Klo + head_base,
                              Vhi + head_base, Vlo + head_base };

    auto issue_chunk = [&](int c) {
        const u32 dbase = smB + BUF_OFF + (u32)(c & 1) * BUF_B;
#pragma unroll
        for (int g = 0; g < 16; g++) {
            int arr = g >> 2;
            int sub = tid + (g & 3) * 256;      // 0..1023
            int row = sub >> 3, q = sub & 7;
            const __half* s = srcs[arr] + ((long)(c * 128 + row)) * HEAD_DIM + q * 8;
            u32 d = dbase + (u32)arr * TILE_B + (u32)(row * FLDT + q * 8) * 2;
            CP_ASYNC16(d, s);
        }
        CP_COMMIT();
    };

    issue_chunk(0);

    const u32 aH = smem_u32(sQh);
    const int r_lo = lane >> 2;
    const int cp2 = (lane & 3) * 2;
    const int row_r = wid * 16 + r_lo;

    float rs0 = 0.f, rs1 = 0.f;
    float o[8][4];
#pragma unroll
    for (int i = 0; i < 8; i++)
#pragma unroll
        for (int e = 0; e < 4; e++) o[i][e] = 0.f;

    for (int c = 0; c < 16; c++) {
        __syncthreads();                      // all warps done with buf[(c+1)&1]
        if (c < 15) {
            issue_chunk(c + 1);
            CP_WAIT1();                        // chunk c landed (own groups)
        } else {
            CP_WAIT0();
        }
        __syncthreads();                      // chunk c visible to all

        const u32 bufb = smB + BUF_OFF + (u32)(c & 1) * BUF_B;
        const u32 bH = bufb;
        const u32 bL = bufb + TILE_B;
        const u32 vH = bufb + 2 * TILE_B;
        const u32 vL = bufb + 3 * TILE_B;

        // ---- QK^T + exp + P store + pack A frags (two 64-key halves) ----
        u32 pa[8][4];
#pragma unroll
        for (int half = 0; half < 2; half++) {
            float sc[8][4];
#pragma unroll
            for (int i = 0; i < 8; i++)
#pragma unroll
                for (int e = 0; e < 4; e++) sc[i][e] = 0.f;

#pragma unroll
            for (int ks = 0; ks < 4; ks++) {
                const int k0 = ks * 16;
                u32 a0, a1, a2, a3;
                {
                    u32 off = (u32)(((wid * 16 + (lane & 15)) * FLDT
                                     + k0 + (lane >> 4) * 8) * 2);
                    ldsm4(a0, a1, a2, a3, aH + off);
                }
#pragma unroll
                for (int np = 0; np < 4; np++) {
                    const int n0 = half * 64 + np * 16;
                    u32 off = (u32)(((n0 + (lane & 7) + ((lane >> 4) << 3)) * FLDT
                                     + k0 + ((lane >> 3) & 1) * 8) * 2);
                    u32 r0, r1, r2, r3;
                    ldsm4(r0, r1, r2, r3, bH + off);
                    mma_f16(sc[np * 2],     a0, a1, a2, a3, r0, r1);
                    mma_f16(sc[np * 2 + 1], a0, a1, a2, a3, r2, r3);
                    ldsm4(r0, r1, r2, r3, bL + off);
                    mma_f16(sc[np * 2],     a0, a1, a2, a3, r0, r1);
                    mma_f16(sc[np * 2 + 1], a0, a1, a2, a3, r2, r3);
                }
            }
#pragma unroll
            for (int ntl = 0; ntl < 8; ntl++) {
                float e0 = fast_exp(sc[ntl][0] * 0.125f);
                float e1 = fast_exp(sc[ntl][1] * 0.125f);
                float e2 = fast_exp(sc[ntl][2] * 0.125f);
                float e3 = fast_exp(sc[ntl][3] * 0.125f);
                rs0 += e0 + e1;
                rs1 += e2 + e3;
                const int n = c * 128 + half * 64 + ntl * 8 + cp2;
                *(float2*)(Pb + (long)row_r * SEQ + n)       = make_float2(e0, e1);
                *(float2*)(Pb + (long)(row_r + 8) * SEQ + n) = make_float2(e2, e3);
                const int kt = half * 4 + (ntl >> 1);
                pa[kt][(ntl & 1) * 2]     = pack_h2(__float2half_rn(e0), __float2half_rn(e1));
                pa[kt][(ntl & 1) * 2 + 1] = pack_h2(__float2half_rn(e2), __float2half_rn(e3));
            }
        }

        // ---- PV: O += E @ V  (V hi + lo, ldmatrix.trans) ----
#pragma unroll
        for (int kt = 0; kt < 8; kt++) {
            const int k0 = kt * 16;
            u32 vh[8][2], vl[8][2];
#pragma unroll
            for (int np2 = 0; np2 < 4; np2++) {
                const int n0 = np2 * 16;
                u32 off = (u32)(((k0 + (lane & 15)) * FLDT + n0 + (lane >> 4) * 8) * 2);
                u32 r0, r1, r2, r3;
                ldsm4t(r0, r1, r2, r3, vH + off);
                vh[np2 * 2][0] = r0; vh[np2 * 2][1] = r1;
                vh[np2 * 2 + 1][0] = r2; vh[np2 * 2 + 1][1] = r3;
                ldsm4t(r0, r1, r2, r3, vL + off);
                vl[np2 * 2][0] = r0; vl[np2 * 2][1] = r1;
                vl[np2 * 2 + 1][0] = r2; vl[np2 * 2 + 1][1] = r3;
            }
#pragma unroll
            for (int nt2 = 0; nt2 < 8; nt2++)
                mma_f16(o[nt2], pa[kt][0], pa[kt][1], pa[kt][2], pa[kt][3],
                        vh[nt2][0], vh[nt2][1]);
#pragma unroll
            for (int nt2 = 0; nt2 < 8; nt2++)
                mma_f16(o[nt2], pa[kt][0], pa[kt][1], pa[kt][2], pa[kt][3],
                        vl[nt2][0], vl[nt2][1]);
        }
    }

    // ---- reduce row sums across the quad ----
    rs0 += __shfl_xor_sync(0xffffffffu, rs0, 1);
    rs0 += __shfl_xor_sync(0xffffffffu, rs0, 2);
    rs1 += __shfl_xor_sync(0xffffffffu, rs1, 1);
    rs1 += __shfl_xor_sync(0xffffffffu, rs1, 2);

    // ---- normalize O, write ctx (fp16 hi) ----
    const float i0 = 1.f / rs0;
    const float i1 = 1.f / rs1;
    {
        const long base0 = ((long)(bb * SEQ + m0 + row_r)) * MODEL_DIM + hh * HEAD_DIM;
        const long base1 = base0 + 8L * MODEL_DIM;
#pragma unroll
        for (int nt2 = 0; nt2 < 8; nt2++) {
            const int col = nt2 * 8 + cp2;
            *(u32*)&ctxh[base0 + col] = pack_h2(__float2half_rn(o[nt2][0] * i0),
                                                __float2half_rn(o[nt2][1] * i0));
            *(u32*)&ctxh[base1 + col] = pack_h2(__float2half_rn(o[nt2][2] * i1),
                                                __float2half_rn(o[nt2][3] * i1));
        }
    }
    if ((lane & 3) == 0) {
        linv[row_r] = i0;
        linv[row_r + 8] = i1;
    }
    __syncthreads();

    // ---- fixup: normalize block's 128x2048 P region (L2-hot) ----
    float4* p4 = (float4*)Pb;
#pragma unroll 4
    for (int idx = tid; idx < 128 * 512; idx += 256) {
        float inv = linv[idx >> 9];
        float4 v = p4[idx];
        v.x *= inv; v.y *= inv; v.z *= inv; v.w *= inv;
        p4[idx] = v;
    }
}

// ============================================================
// Host launch
// ============================================================
extern "C" void kernel_launch(void* const* d_in, const int* in_sizes, int n_in,
                              void* d_out, int out_size)
{
    const float* q    = (const float*)d_in[0];
    const float* k    = (const float*)d_in[1];
    const float* v    = (const float*)d_in[2];
    const float* wq_w = (const float*)d_in[3];
    const float* wq_b = (const float*)d_in[4];
    const float* wk_w = (const float*)d_in[5];
    const float* wk_b = (const float*)d_in[6];
    const float* wv_w = (const float*)d_in[7];
    const float* wv_b = (const float*)d_in[8];
    const float* wo_w = (const float*)d_in[9];
    const float* wo_b = (const float*)d_in[10];
    float* out = (float*)d_out;

    __half *qhi, *khi, *klo, *vhi, *vlo, *ctxh;
    cudaGetSymbolAddress((void**)&qhi, g_qhi);
    cudaGetSymbolAddress((void**)&khi, g_khi);
    cudaGetSymbolAddress((void**)&klo, g_klo);
    cudaGetSymbolAddress((void**)&vhi, g_vhi);
    cudaGetSymbolAddress((void**)&vlo, g_vlo);
    cudaGetSymbolAddress((void**)&ctxh, g_ctxh);

    float* attnW = out + (long)M_TOT * MODEL_DIM;

    const int SMEM_OUT = (2 * 128 * LDT + 4 * 128 * LDT) * 2;   // 61440 B

    cudaFuncSetAttribute(fused_attn,
                         cudaFuncAttributeMaxDynamicSharedMemorySize, FA_SMEM);
    cudaFuncSetAttribute(out_gemm,
                         cudaFuncAttributeMaxDynamicSharedMemorySize, SMEM_OUT);

    dim3 gqkv(M_TOT / 128, MODEL_DIM / 128, 3);           // (32, 6, 3)
    qkv_gemm<<<gqkv, 256>>>(q, k, v, wq_w, wk_w, wv_w,
                            wq_b, wk_b, wv_b, qhi, khi, klo, vhi, vlo);

    dim3 gfa(SEQ / 128, BHEADS);                          // (16, 24)
    fused_attn<<<gfa, 256, FA_SMEM>>>(qhi, khi, klo, vhi, vlo, attnW, ctxh);

    dim3 gout(M_TOT / 128, MODEL_DIM / 128, 1);           // (32, 6)
    out_gemm<<<gout, 256, SMEM_OUT>>>(ctxh, wo_w, wo_b, out);
}